// round 9
// baseline (speedup 1.0000x reference)
#include <cuda_runtime.h>
#include <cuda_bf16.h>
#include <math.h>
#include <stdint.h>

// ---------------------------------------------------------------------------
// B=2, 32x32 spatial (L=1024, S=2048), out_dim=384, Di=768, N=16, R=48, K=4
// ---------------------------------------------------------------------------

#define S_TOT 2048
#define L_LEN 1024
#define DI    768
#define DOUT  384
#define NST   16
#define CT    80
#define RLOW  48

// weight arena offsets (elements)
#define W_PE  0
#define W_LP  1179648
#define W_IN  1474560
#define W_XP  2654208
#define W_DT  3145728
#define W_OUT 3440640
#define W_TOT 4030464

// ------------------------- scratch ------------------------------------------
__device__ __align__(16) __nv_bfloat16 g_whi[W_TOT];
__device__ __align__(16) __nv_bfloat16 g_wlo[W_TOT];

__device__ __align__(16) __nv_bfloat16 g_xT_hi[2 * 256 * 768],  g_xT_lo[2 * 256 * 768];
__device__ __align__(16) __nv_bfloat16 g_cat_hi[S_TOT * 768],   g_cat_lo[S_TOT * 768];
__device__ __align__(16) __nv_bfloat16 g_h_hi[S_TOT * DOUT],    g_h_lo[S_TOT * DOUT];
__device__ __align__(16) __nv_bfloat16 g_xc_hi[S_TOT * DI],     g_xc_lo[S_TOT * DI];
__device__ __align__(16) __nv_bfloat16 g_xd_hi[8 * L_LEN * CT], g_xd_lo[8 * L_LEN * CT];
__device__ __align__(16) __nv_bfloat16 g_y_hi[S_TOT * DI],      g_y_lo[S_TOT * DI];

__device__ float g_pe  [512 * 1536];
__device__ float g_xh  [S_TOT * DOUT];
__device__ float g_xz  [S_TOT * 1536];
__device__ float g_xc  [S_TOT * DI];
__device__ float g_xdbl[8 * L_LEN * CT];
__device__ float g_dts [8 * L_LEN * DI];
__device__ float g_ys  [8 * L_LEN * DI];
__device__ int   g_rowmap[8 * L_LEN];

// ------------------------- helpers ------------------------------------------
__device__ __forceinline__ float block_reduce_sum(float v, float* red) {
#pragma unroll
    for (int o = 16; o > 0; o >>= 1) v += __shfl_xor_sync(0xffffffffu, v, o);
    int warp = threadIdx.x >> 5;
    if ((threadIdx.x & 31) == 0) red[warp] = v;
    __syncthreads();
    int nw = blockDim.x >> 5;
    float s = 0.f;
    for (int i = 0; i < nw; i++) s += red[i];
    __syncthreads();
    return s;
}

__device__ __forceinline__ int swap_l(int l) { return ((l & 31) << 5) | (l >> 5); }
__device__ __forceinline__ float silu_f(float v) { return v / (1.f + __expf(-v)); }

__device__ __forceinline__ void split1(float f, __nv_bfloat16* hp, __nv_bfloat16* lp) {
    __nv_bfloat16 h = __float2bfloat16(f);
    *hp = h;
    *lp = __float2bfloat16(f - __bfloat162float(h));
}
__device__ __forceinline__ void split2(float f0, float f1, unsigned& hi, unsigned& lo) {
    __nv_bfloat162 h = __floats2bfloat162_rn(f0, f1);
    float h0 = __low2float(h), h1 = __high2float(h);
    __nv_bfloat162 l = __floats2bfloat162_rn(f0 - h0, f1 - h1);
    hi = *(unsigned*)&h;
    lo = *(unsigned*)&l;
}

__device__ __forceinline__ void mma16816(float* d, const unsigned* a, const unsigned* b) {
    asm volatile(
        "mma.sync.aligned.m16n8k16.row.col.f32.bf16.bf16.f32 "
        "{%0,%1,%2,%3}, {%4,%5,%6,%7}, {%8,%9}, {%0,%1,%2,%3};"
        : "+f"(d[0]), "+f"(d[1]), "+f"(d[2]), "+f"(d[3])
        : "r"(a[0]), "r"(a[1]), "r"(a[2]), "r"(a[3]), "r"(b[0]), "r"(b[1]));
}

__device__ __forceinline__ void ldsm4(unsigned* r, unsigned addr) {
    asm volatile("ldmatrix.sync.aligned.m8n8.x4.shared.b16 {%0,%1,%2,%3}, [%4];"
                 : "=r"(r[0]), "=r"(r[1]), "=r"(r[2]), "=r"(r[3]) : "r"(addr));
}

__device__ __forceinline__ void cpa16(unsigned smem, const void* g, int srcBytes) {
    asm volatile("cp.async.cg.shared.global [%0], [%1], 16, %2;\n"
                 :: "r"(smem), "l"(g), "r"(srcBytes));
}
__device__ __forceinline__ void cpa_commit() { asm volatile("cp.async.commit_group;\n"); }
template <int N>
__device__ __forceinline__ void cpa_wait() { asm volatile("cp.async.wait_group %0;\n" :: "n"(N)); }

// ------------------------- weight conversion --------------------------------
__global__ void convert_weights(const float* __restrict__ pe_w, const float* __restrict__ lp_w,
                                const float* __restrict__ in_w, const float* __restrict__ xp_w,
                                const float* __restrict__ dt_w, const float* __restrict__ out_w)
{
    int idx = blockIdx.x * blockDim.x + threadIdx.x;
    if (idx >= W_TOT) return;
    float v;
    if      (idx < W_LP)  v = pe_w[idx - W_PE];
    else if (idx < W_IN)  v = lp_w[idx - W_LP];
    else if (idx < W_XP)  v = in_w[idx - W_IN];
    else if (idx < W_DT)  v = xp_w[idx - W_XP];
    else if (idx < W_OUT) v = dt_w[idx - W_DT];
    else                  v = out_w[idx - W_OUT];
    split1(v, &g_whi[idx], &g_wlo[idx]);
}

// ---------------- all-bf16 split tensor-core GEMM: C = A * W^T --------------
// 128 threads, 4 warps (1x4), warp tile 32x16, block tile 32x64x32,
// 3-stage cp.async pipeline, ldmatrix + kk fragment double-buffer.
// flags: 1 = +bias[col], 2 = softplus, 4 = accumulate C, 8 = split bf16 out.
#define GBM 32
#define GBN 64
#define GBK 32
#define GSR 20          // words per smem row (16 data + 4 pad)
#define NSTG 3
#define ASTG (GBM * GSR * 4)   // bytes per A stage
#define WSTG (GBN * GSR * 4)   // bytes per W stage

__global__ void gemm_bf(const __nv_bfloat16* __restrict__ Ahi, const __nv_bfloat16* __restrict__ Alo,
                        const __nv_bfloat16* __restrict__ Whi, const __nv_bfloat16* __restrict__ Wlo,
                        const float* __restrict__ bias, float* __restrict__ C,
                        __nv_bfloat16* __restrict__ SpH, __nv_bfloat16* __restrict__ SpL,
                        int M, int Ncols, int Kdim, int lda, int ldw, int ldc,
                        long aBatch, long wBatch, int wMod, long biasBatch, long cBatch,
                        const int* __restrict__ rowmap, int rmBatch, int flags)
{
    __shared__ unsigned AsH[NSTG][GBM][GSR], AsL[NSTG][GBM][GSR];
    __shared__ unsigned WsH[NSTG][GBN][GSR], WsL[NSTG][GBN][GSR];

    const int z = blockIdx.z;
    const int wz = (wMod > 1) ? (z % wMod) : 0;
    const __nv_bfloat16* AhB = Ahi + (long)z * aBatch;
    const __nv_bfloat16* AlB = Alo + (long)z * aBatch;
    const __nv_bfloat16* WhB = Whi + (long)wz * wBatch;
    const __nv_bfloat16* WlB = Wlo + (long)wz * wBatch;
    const float* biasb = bias ? (bias + (long)wz * biasBatch) : (const float*)0;
    float* Cb = C + (long)z * cBatch;
    const int* rm = rowmap ? (rowmap + (long)z * rmBatch) : (const int*)0;

    const int m0 = blockIdx.y * GBM, n0 = blockIdx.x * GBN;
    const int tid = threadIdx.x;
    const int wid = tid >> 5, lane = tid & 31;
    const int wn = wid * 16;
    const int gq = lane >> 2, qq = lane & 3;

    // A loader: 1 chunk (8 bf16 = 16B) per thread
    const int arowLoc = tid >> 2;          // 0..31
    const int akc = (tid & 3) * 8;
    int arow = m0 + arowLoc;
    if (rm) arow = rm[arow];
    const __nv_bfloat16* pAh = AhB + (long)arow * lda + akc;
    const __nv_bfloat16* pAl = AlB + (long)arow * lda + akc;
    const unsigned aOff = (unsigned)((arowLoc * GSR + (akc >> 1)) * 4);

    // W loader: 2 chunks per thread
    int wkc0 = ((tid * 2) & 3) * 8, wkc1 = ((tid * 2 + 1) & 3) * 8;
    int wrl0 = (tid * 2) >> 2,      wrl1 = (tid * 2 + 1) >> 2;
    bool wv0 = (n0 + wrl0) < Ncols, wv1 = (n0 + wrl1) < Ncols;
    const __nv_bfloat16* pWh0 = WhB + (long)(wv0 ? n0 + wrl0 : 0) * ldw + wkc0;
    const __nv_bfloat16* pWl0 = WlB + (long)(wv0 ? n0 + wrl0 : 0) * ldw + wkc0;
    const __nv_bfloat16* pWh1 = WhB + (long)(wv1 ? n0 + wrl1 : 0) * ldw + wkc1;
    const __nv_bfloat16* pWl1 = WlB + (long)(wv1 ? n0 + wrl1 : 0) * ldw + wkc1;
    const unsigned wOff0 = (unsigned)((wrl0 * GSR + (wkc0 >> 1)) * 4);
    const unsigned wOff1 = (unsigned)((wrl1 * GSR + (wkc1 >> 1)) * 4);

    unsigned bAsH = (unsigned)__cvta_generic_to_shared(&AsH[0][0][0]);
    unsigned bAsL = (unsigned)__cvta_generic_to_shared(&AsL[0][0][0]);
    unsigned bWsH = (unsigned)__cvta_generic_to_shared(&WsH[0][0][0]);
    unsigned bWsL = (unsigned)__cvta_generic_to_shared(&WsL[0][0][0]);

    float acc[2][2][4];
#pragma unroll
    for (int i = 0; i < 2; i++)
#pragma unroll
        for (int j = 0; j < 2; j++)
#pragma unroll
            for (int f = 0; f < 4; f++) acc[i][j][f] = 0.f;

    const int T = (Kdim + GBK - 1) / GBK;

    // ldmatrix lane addressing
    const unsigned aRowSel = (unsigned)(lane & 15);
    const unsigned aColSel = (unsigned)((lane >> 4) * 4);
    const unsigned bRowSel = (unsigned)(((lane >> 4) << 3) + (lane & 7));
    const unsigned bColSel = (unsigned)(((lane >> 3) & 1) * 4);

#define GEMM_ISSUE(tt)                                                          \
    {                                                                           \
        int k0_ = (tt) * GBK;                                                   \
        unsigned sA_ = (unsigned)((tt) % NSTG) * ASTG;                          \
        unsigned sW_ = (unsigned)((tt) % NSTG) * WSTG;                          \
        int kbA_ = (k0_ + akc + 8 <= Kdim) ? 16 : 0;                            \
        cpa16(bAsH + sA_ + aOff, pAh + k0_, kbA_);                              \
        cpa16(bAsL + sA_ + aOff, pAl + k0_, kbA_);                              \
        int kb0_ = (wv0 && (k0_ + wkc0 + 8 <= Kdim)) ? 16 : 0;                  \
        int kb1_ = (wv1 && (k0_ + wkc1 + 8 <= Kdim)) ? 16 : 0;                  \
        cpa16(bWsH + sW_ + wOff0, pWh0 + k0_, kb0_);                            \
        cpa16(bWsL + sW_ + wOff0, pWl0 + k0_, kb0_);                            \
        cpa16(bWsH + sW_ + wOff1, pWh1 + k0_, kb1_);                            \
        cpa16(bWsL + sW_ + wOff1, pWl1 + k0_, kb1_);                            \
        cpa_commit();                                                           \
    }

    GEMM_ISSUE(0);
    if (T > 1) GEMM_ISSUE(1);

    for (int t = 0; t < T; t++) {
        if (t + 1 < T) cpa_wait<1>(); else cpa_wait<0>();
        __syncthreads();
        if (t + 2 < T) GEMM_ISSUE(t + 2);

        unsigned sA = (unsigned)(t % NSTG) * ASTG;
        unsigned sW = (unsigned)(t % NSTG) * WSTG;

        unsigned fAh[2][2][4], fAl[2][2][4], fBh[2][4], fBl[2][4];
        // load kk=0 fragments
#pragma unroll
        for (int i = 0; i < 2; i++) {
            unsigned ar = ((unsigned)(i * 16) + aRowSel) * GSR + aColSel;
            ldsm4(fAh[0][i], bAsH + sA + (ar << 2));
            ldsm4(fAl[0][i], bAsL + sA + (ar << 2));
        }
        {
            unsigned br = ((unsigned)wn + bRowSel) * GSR + bColSel;
            ldsm4(fBh[0], bWsH + sW + (br << 2));
            ldsm4(fBl[0], bWsL + sW + (br << 2));
        }
#pragma unroll
        for (int kk = 0; kk < 2; kk++) {
            if (kk == 0) {   // prefetch kk=1 fragments
#pragma unroll
                for (int i = 0; i < 2; i++) {
                    unsigned ar = ((unsigned)(i * 16) + aRowSel) * GSR + 8 + aColSel;
                    ldsm4(fAh[1][i], bAsH + sA + (ar << 2));
                    ldsm4(fAl[1][i], bAsL + sA + (ar << 2));
                }
                unsigned br = ((unsigned)wn + bRowSel) * GSR + 8 + bColSel;
                ldsm4(fBh[1], bWsH + sW + (br << 2));
                ldsm4(fBl[1], bWsL + sW + (br << 2));
            }
#pragma unroll
            for (int i = 0; i < 2; i++)
#pragma unroll
                for (int j = 0; j < 2; j++) {
                    mma16816(acc[i][j], fAh[kk][i], fBh[kk] + j * 2);
                    mma16816(acc[i][j], fAh[kk][i], fBl[kk] + j * 2);
                    mma16816(acc[i][j], fAl[kk][i], fBh[kk] + j * 2);
                }
        }
    }

    // ------------------------------ epilogue --------------------------------
    __nv_bfloat16* SpHb = SpH ? (SpH + (long)z * cBatch) : (__nv_bfloat16*)0;
    __nv_bfloat16* SpLb = SpL ? (SpL + (long)z * cBatch) : (__nv_bfloat16*)0;
#pragma unroll
    for (int i = 0; i < 2; i++) {
        int r0 = m0 + i * 16 + gq;
        int r1 = r0 + 8;
#pragma unroll
        for (int j = 0; j < 2; j++) {
            int col = n0 + wn + j * 8 + qq * 2;
            if (col >= Ncols) continue;
            float v0 = acc[i][j][0], v1 = acc[i][j][1];
            float v2 = acc[i][j][2], v3 = acc[i][j][3];
            if (flags & 1) {
                float b0 = biasb[col], b1 = biasb[col + 1];
                v0 += b0; v1 += b1; v2 += b0; v3 += b1;
            }
            if (flags & 2) {
                v0 = (v0 > 20.f) ? v0 : log1pf(__expf(v0));
                v1 = (v1 > 20.f) ? v1 : log1pf(__expf(v1));
                v2 = (v2 > 20.f) ? v2 : log1pf(__expf(v2));
                v3 = (v3 > 20.f) ? v3 : log1pf(__expf(v3));
            }
            float2* p0 = (float2*)&Cb[(long)r0 * ldc + col];
            float2* p1 = (float2*)&Cb[(long)r1 * ldc + col];
            if (flags & 4) {
                float2 o0 = *p0, o1 = *p1;
                v0 += o0.x; v1 += o0.y; v2 += o1.x; v3 += o1.y;
            }
            *p0 = make_float2(v0, v1);
            *p1 = make_float2(v2, v3);
            if (flags & 8) {
                unsigned h, l;
                split2(v0, v1, h, l);
                *(unsigned*)&SpHb[(long)r0 * ldc + col] = h;
                *(unsigned*)&SpLb[(long)r0 * ldc + col] = l;
                split2(v2, v3, h, l);
                *(unsigned*)&SpHb[(long)r1 * ldc + col] = h;
                *(unsigned*)&SpLb[(long)r1 * ldc + col] = l;
            }
        }
    }
}

// ------------------------- transposes ---------------------------------------
__global__ void transpose_split_kernel(const float* __restrict__ src,
                                       __nv_bfloat16* __restrict__ dhi,
                                       __nv_bfloat16* __restrict__ dlo,
                                       int rows, int cols)
{
    __shared__ float tile[32][33];
    int c0 = blockIdx.x * 32, r0 = blockIdx.y * 32, bz = blockIdx.z;
    const float* s = src + (long)bz * rows * cols;
    long dbase = (long)bz * rows * cols;
    for (int i = threadIdx.y; i < 32; i += 8)
        tile[i][threadIdx.x] = s[(long)(r0 + i) * cols + c0 + threadIdx.x];
    __syncthreads();
    for (int i = threadIdx.y; i < 32; i += 8) {
        long di = dbase + (long)(c0 + i) * rows + r0 + threadIdx.x;
        split1(tile[threadIdx.x][i], &dhi[di], &dlo[di]);
    }
}

__global__ void transpose_kernel(const float* __restrict__ src, float* __restrict__ dst,
                                 int rows, int cols)
{
    __shared__ float tile[32][33];
    int c0 = blockIdx.x * 32, r0 = blockIdx.y * 32, bz = blockIdx.z;
    const float* s = src + (long)bz * rows * cols;
    float* d = dst + (long)bz * rows * cols;
    for (int i = threadIdx.y; i < 32; i += 8)
        tile[i][threadIdx.x] = s[(long)(r0 + i) * cols + c0 + threadIdx.x];
    __syncthreads();
    for (int i = threadIdx.y; i < 32; i += 8)
        d[(long)(c0 + i) * rows + r0 + threadIdx.x] = tile[threadIdx.x][i];
}

// ------------------------- rowmap init --------------------------------------
__global__ void rowmap_init()
{
    int g = blockIdx.x, l = threadIdx.x;
    int k = g & 3, b = g >> 2;
    int s;
    if (k == 0) s = l;
    else if (k == 1) s = swap_l(l);
    else if (k == 2) s = 1023 - l;
    else { int m = 1023 - l; s = swap_l(m); }
    g_rowmap[g * L_LEN + l] = b * L_LEN + s;
}

// ------------------------- patch-expand LN + concat skip --------------------
__global__ void pe_cat_kernel(const float* __restrict__ pe, const float* __restrict__ skip,
                              const float* __restrict__ nw, const float* __restrict__ nb)
{
    int pix = blockIdx.x;
    int b = pix >> 10, Y = (pix >> 5) & 31, X = pix & 31;
    int h = Y >> 1, p = Y & 1, w = X >> 1, q = X & 1;
    const float* src = pe + (long)(b * 256 + h * 16 + w) * 1536 + (p * 2 + q) * 384;

    __shared__ float red[32];
    float v[3]; float ssum = 0.f;
#pragma unroll
    for (int j = 0; j < 3; j++) { v[j] = src[threadIdx.x + j * 128]; ssum += v[j]; }
    float mean = block_reduce_sum(ssum, red) * (1.f / 384.f);
    float vs = 0.f;
#pragma unroll
    for (int j = 0; j < 3; j++) { float d = v[j] - mean; vs += d * d; }
    float var = block_reduce_sum(vs, red) * (1.f / 384.f);
    float rstd = rsqrtf(var + 1e-5f);

    long dbase = (long)pix * 768;
#pragma unroll
    for (int j = 0; j < 3; j++) {
        int c = threadIdx.x + j * 128;
        split1((v[j] - mean) * rstd * nw[c] + nb[c], &g_cat_hi[dbase + c], &g_cat_lo[dbase + c]);
    }
    const float* sp = skip + (long)b * 384 * 1024 + (Y * 32 + X);
#pragma unroll
    for (int j = 0; j < 3; j++) {
        int c = threadIdx.x + j * 128;
        split1(sp[(long)c * 1024], &g_cat_hi[dbase + 384 + c], &g_cat_lo[dbase + 384 + c]);
    }
}

// ------------------------- LN over 384 (split output) ------------------------
__global__ void ln384_kernel(const float* __restrict__ in,
                             const float* __restrict__ w, const float* __restrict__ b)
{
    int row = blockIdx.x;
    const float* src = in + (long)row * 384;
    __shared__ float red[32];
    float v[3]; float ssum = 0.f;
#pragma unroll
    for (int j = 0; j < 3; j++) { v[j] = src[threadIdx.x + j * 128]; ssum += v[j]; }
    float mean = block_reduce_sum(ssum, red) * (1.f / 384.f);
    float vs = 0.f;
#pragma unroll
    for (int j = 0; j < 3; j++) { float d = v[j] - mean; vs += d * d; }
    float var = block_reduce_sum(vs, red) * (1.f / 384.f);
    float rstd = rsqrtf(var + 1e-5f);
    long dbase = (long)row * 384;
#pragma unroll
    for (int j = 0; j < 3; j++) {
        int c = threadIdx.x + j * 128;
        split1((v[j] - mean) * rstd * w[c] + b[c], &g_h_hi[dbase + c], &g_h_lo[dbase + c]);
    }
}

// ------------------------- conv + silu (fp32 + split outputs) ----------------
__global__ void conv_kernel(const float* __restrict__ xz, const float* __restrict__ cw,
                            const float* __restrict__ cb, float* __restrict__ xc)
{
    int pix = blockIdx.x;
    int b = pix >> 10, Y = (pix >> 5) & 31, X = pix & 31;
    int t = threadIdx.x;
    float acc[3] = {0.f, 0.f, 0.f};
    for (int dy = -1; dy <= 1; dy++) {
        int yy = Y + dy; if ((unsigned)yy >= 32u) continue;
        for (int dx = -1; dx <= 1; dx++) {
            int xx = X + dx; if ((unsigned)xx >= 32u) continue;
            const float* row = xz + (long)(b * 1024 + yy * 32 + xx) * 1536;
            int widx = (dy + 1) * 3 + (dx + 1);
#pragma unroll
            for (int j = 0; j < 3; j++) {
                int c = t + j * 256;
                acc[j] = fmaf(row[c], cw[c * 9 + widx], acc[j]);
            }
        }
    }
    long dbase = (long)pix * 768;
#pragma unroll
    for (int j = 0; j < 3; j++) {
        int c = t + j * 256;
        float v = silu_f(acc[j] + cb[c]);
        xc[dbase + c] = v;
        split1(v, &g_xc_hi[dbase + c], &g_xc_lo[dbase + c]);
    }
}

// ------------------------- selective scan (software-pipelined) ---------------
__device__ __forceinline__ int scan_map(int k, int l) {
    if (k == 0) return l;
    if (k == 1) return swap_l(l);
    if (k == 2) return 1023 - l;
    return swap_l(1023 - l);
}

__global__ void scan_kernel(const float* __restrict__ dts, const float* __restrict__ xc,
                            const float* __restrict__ xdbl, const float* __restrict__ A_log,
                            const float* __restrict__ Ds, float* __restrict__ ys)
{
    int g = blockIdx.x;
    int k = g & 3, b = g >> 2;
    int tid = threadIdx.x;
    int n = tid & 15;
    int d = blockIdx.y * 8 + (tid >> 4);

    float A = -__expf(A_log[((long)(k * DI + d)) * NST + n]);
    float h = 0.f;
    float Dv = Ds[k * DI + d];

    const float* dtp = dts + (long)g * L_LEN * DI + d;
    const float* xdp = xdbl + (long)g * L_LEN * CT;
    const float* xcb = xc + (long)b * L_LEN * DI + d;
    float* yp = ys + (long)g * L_LEN * DI + d;

    // prefetch iteration 0
    int s0 = scan_map(k, 0);
    float dt_c = dtp[0];
    float u_c  = xcb[(long)s0 * DI];
    float B_c  = xdp[RLOW + n];
    float C_c  = xdp[RLOW + NST + n];

    for (int l = 0; l < L_LEN; l++) {
        float dt_n = 0.f, u_n = 0.f, B_n = 0.f, C_n = 0.f;
        int ln = l + 1;
        if (ln < L_LEN) {
            int sn = scan_map(k, ln);
            dt_n = dtp[(long)ln * DI];
            u_n  = xcb[(long)sn * DI];
            const float* bc = xdp + ln * CT;
            B_n = bc[RLOW + n];
            C_n = bc[RLOW + NST + n];
        }
        float e = __expf(dt_c * A);
        h = fmaf(e, h, dt_c * u_c * B_c);
        float t = h * C_c;
        t += __shfl_xor_sync(0xffffffffu, t, 1);
        t += __shfl_xor_sync(0xffffffffu, t, 2);
        t += __shfl_xor_sync(0xffffffffu, t, 4);
        t += __shfl_xor_sync(0xffffffffu, t, 8);
        if (n == 0) yp[(long)l * DI] = fmaf(Dv, u_c, t);
        dt_c = dt_n; u_c = u_n; B_c = B_n; C_c = C_n;
    }
}

// ------------------------- combine + out-LN + silu gate (split out) ----------
__global__ void combine_kernel(const float* __restrict__ ys, const float* __restrict__ xz,
                               const float* __restrict__ onw, const float* __restrict__ onb)
{
    int bs = blockIdx.x;
    int b = bs >> 10, s = bs & 1023;
    int sw = swap_l(s);
    long base0 = ((long)(b * 4 + 0) * L_LEN + s)          * DI;
    long base1 = ((long)(b * 4 + 1) * L_LEN + sw)         * DI;
    long base2 = ((long)(b * 4 + 2) * L_LEN + (1023 - s)) * DI;
    long base3 = ((long)(b * 4 + 3) * L_LEN + (1023 - sw))* DI;

    __shared__ float red[32];
    float v[3]; float ssum = 0.f;
#pragma unroll
    for (int j = 0; j < 3; j++) {
        int c = threadIdx.x + j * 256;
        v[j] = ys[base0 + c] + ys[base1 + c] + ys[base2 + c] + ys[base3 + c];
        ssum += v[j];
    }
    float mean = block_reduce_sum(ssum, red) * (1.f / 768.f);
    float vs = 0.f;
#pragma unroll
    for (int j = 0; j < 3; j++) { float d = v[j] - mean; vs += d * d; }
    float var = block_reduce_sum(vs, red) * (1.f / 768.f);
    float rstd = rsqrtf(var + 1e-5f);

    long dbase = (long)bs * DI;
#pragma unroll
    for (int j = 0; j < 3; j++) {
        int c = threadIdx.x + j * 256;
        float zz = xz[(long)bs * 1536 + 768 + c];
        float r = ((v[j] - mean) * rstd * onw[c] + onb[c]) * silu_f(zz);
        split1(r, &g_y_hi[dbase + c], &g_y_lo[dbase + c]);
    }
}

// ---------------------------------------------------------------------------
extern "C" void kernel_launch(void* const* d_in, const int* in_sizes, int n_in,
                              void* d_out, int out_size)
{
    const float* x      = (const float*)d_in[0];
    const float* skip   = (const float*)d_in[1];
    const float* pe_w   = (const float*)d_in[2];
    const float* pe_nw  = (const float*)d_in[3];
    const float* pe_nb  = (const float*)d_in[4];
    const float* lp_w   = (const float*)d_in[5];
    const float* lp_b   = (const float*)d_in[6];
    const float* bln_w  = (const float*)d_in[7];
    const float* bln_b  = (const float*)d_in[8];
    const float* in_w   = (const float*)d_in[9];
    const float* conv_w = (const float*)d_in[10];
    const float* conv_b = (const float*)d_in[11];
    const float* xp_w   = (const float*)d_in[12];
    const float* dt_w   = (const float*)d_in[13];
    const float* dt_b   = (const float*)d_in[14];
    const float* A_log  = (const float*)d_in[15];
    const float* Ds     = (const float*)d_in[16];
    const float* on_w   = (const float*)d_in[17];
    const float* on_b   = (const float*)d_in[18];
    const float* out_w  = (const float*)d_in[19];
    float* out = (float*)d_out;

    float *pe, *xh, *xz, *xc, *xdbl, *dts, *ys;
    int* rowmap;
    __nv_bfloat16 *whi, *wlo, *xTh, *xTl, *cath, *catl, *hh, *hl, *xch, *xcl, *xdh, *xdl, *yh, *yl;
    cudaGetSymbolAddress((void**)&pe,   g_pe);
    cudaGetSymbolAddress((void**)&xh,   g_xh);
    cudaGetSymbolAddress((void**)&xz,   g_xz);
    cudaGetSymbolAddress((void**)&xc,   g_xc);
    cudaGetSymbolAddress((void**)&xdbl, g_xdbl);
    cudaGetSymbolAddress((void**)&dts,  g_dts);
    cudaGetSymbolAddress((void**)&ys,   g_ys);
    cudaGetSymbolAddress((void**)&rowmap, g_rowmap);
    cudaGetSymbolAddress((void**)&whi,  g_whi);
    cudaGetSymbolAddress((void**)&wlo,  g_wlo);
    cudaGetSymbolAddress((void**)&xTh,  g_xT_hi);
    cudaGetSymbolAddress((void**)&xTl,  g_xT_lo);
    cudaGetSymbolAddress((void**)&cath, g_cat_hi);
    cudaGetSymbolAddress((void**)&catl, g_cat_lo);
    cudaGetSymbolAddress((void**)&hh,   g_h_hi);
    cudaGetSymbolAddress((void**)&hl,   g_h_lo);
    cudaGetSymbolAddress((void**)&xch,  g_xc_hi);
    cudaGetSymbolAddress((void**)&xcl,  g_xc_lo);
    cudaGetSymbolAddress((void**)&xdh,  g_xd_hi);
    cudaGetSymbolAddress((void**)&xdl,  g_xd_lo);
    cudaGetSymbolAddress((void**)&yh,   g_y_hi);
    cudaGetSymbolAddress((void**)&yl,   g_y_lo);

    convert_weights<<<(W_TOT + 255) / 256, 256>>>(pe_w, lp_w, in_w, xp_w, dt_w, out_w);
    transpose_split_kernel<<<dim3(8, 24, 2), dim3(32, 8)>>>(x, xTh, xTl, 768, 256);
    rowmap_init<<<8, 1024>>>();

    // patch-expand GEMM: (512 x 1536 x 768)  grid 24x16 = 384
    gemm_bf<<<dim3(24, 16, 1), 128>>>(xTh, xTl, whi + W_PE, wlo + W_PE, nullptr, pe,
                                      nullptr, nullptr, 512, 1536, 768, 768, 768, 1536,
                                      0, 0, 1, 0, 0, nullptr, 0, 0);
    pe_cat_kernel<<<2048, 128>>>(pe, skip, pe_nw, pe_nb);
    // linear proj: (2048 x 384 x 768) + bias  grid 6x64 = 384
    gemm_bf<<<dim3(6, 64, 1), 128>>>(cath, catl, whi + W_LP, wlo + W_LP, lp_b, xh,
                                     nullptr, nullptr, 2048, 384, 768, 768, 768, 384,
                                     0, 0, 1, 0, 0, nullptr, 0, 1);

    for (int layer = 0; layer < 2; layer++) {
        ln384_kernel<<<2048, 128>>>(xh, bln_w + layer * 384, bln_b + layer * 384);
        // in_proj: (2048 x 1536 x 384)  grid 24x64 = 1536
        gemm_bf<<<dim3(24, 64, 1), 128>>>(hh, hl, whi + W_IN + (long)layer * 589824,
                                          wlo + W_IN + (long)layer * 589824, nullptr, xz,
                                          nullptr, nullptr, 2048, 1536, 384, 384, 384, 1536,
                                          0, 0, 1, 0, 0, nullptr, 0, 0);
        conv_kernel<<<2048, 256>>>(xz, conv_w + (long)layer * 768 * 9,
                                   conv_b + layer * 768, xc);
        // x_proj: 8 x (1024 x 80 x 768)  grid 2x32x8 = 512
        gemm_bf<<<dim3(2, 32, 8), 128>>>(xch, xcl, whi + W_XP + (long)layer * 245760,
                                         wlo + W_XP + (long)layer * 245760, nullptr, xdbl,
                                         xdh, xdl, 1024, 80, 768, 768, 768, 80,
                                         0, 61440, 4, 0, 81920, rowmap, 1024, 8);
        // dt_proj: 8 x (1024 x 768 x 48) + bias + softplus  grid 12x32x8 = 3072
        gemm_bf<<<dim3(12, 32, 8), 128>>>(xdh, xdl, whi + W_DT + (long)layer * 147456,
                                          wlo + W_DT + (long)layer * 147456,
                                          dt_b + (long)layer * 3072, dts,
                                          nullptr, nullptr, 1024, 768, 48, 80, 48, 768,
                                          81920, 36864, 4, 768, 786432, nullptr, 0, 1 | 2);
        scan_kernel<<<dim3(8, 96), 128>>>(dts, xc, xdbl,
                                          A_log + (long)layer * 4 * 768 * 16,
                                          Ds + (long)layer * 4 * 768, ys);
        combine_kernel<<<2048, 256>>>(ys, xz, on_w + layer * 768, on_b + layer * 768);
        // out_proj + residual: (2048 x 384 x 768)  grid 6x64 = 384
        gemm_bf<<<dim3(6, 64, 1), 128>>>(yh, yl, whi + W_OUT + (long)layer * 294912,
                                         wlo + W_OUT + (long)layer * 294912, nullptr, xh,
                                         nullptr, nullptr, 2048, 384, 768, 768, 768, 384,
                                         0, 0, 1, 0, 0, nullptr, 0, 4);
    }

    transpose_kernel<<<dim3(12, 32, 2), dim3(32, 8)>>>(xh, out, 1024, 384);
}

// round 10
// speedup vs baseline: 1.6487x; 1.6487x over previous
#include <cuda_runtime.h>
#include <cuda_bf16.h>
#include <math.h>
#include <stdint.h>

// ---------------------------------------------------------------------------
// B=2, 32x32 spatial (L=1024, S=2048), out_dim=384, Di=768, N=16, R=48, K=4
// ---------------------------------------------------------------------------

#define S_TOT 2048
#define L_LEN 1024
#define DI    768
#define DOUT  384
#define NST   16
#define CT    80
#define RLOW  48
#define NCHK  16
#define CLEN  64

// weight arena offsets (elements)
#define W_PE  0
#define W_LP  1179648
#define W_IN  1474560
#define W_XP  2654208
#define W_DT  3145728
#define W_OUT 3440640
#define W_TOT 4030464

// ------------------------- scratch ------------------------------------------
__device__ __align__(16) __nv_bfloat16 g_whi[W_TOT];
__device__ __align__(16) __nv_bfloat16 g_wlo[W_TOT];

__device__ __align__(16) __nv_bfloat16 g_xT_hi[2 * 256 * 768],  g_xT_lo[2 * 256 * 768];
__device__ __align__(16) __nv_bfloat16 g_cat_hi[S_TOT * 768],   g_cat_lo[S_TOT * 768];
__device__ __align__(16) __nv_bfloat16 g_h_hi[S_TOT * DOUT],    g_h_lo[S_TOT * DOUT];
__device__ __align__(16) __nv_bfloat16 g_xc_hi[S_TOT * DI],     g_xc_lo[S_TOT * DI];
__device__ __align__(16) __nv_bfloat16 g_xd_hi[8 * L_LEN * CT], g_xd_lo[8 * L_LEN * CT];
__device__ __align__(16) __nv_bfloat16 g_y_hi[S_TOT * DI],      g_y_lo[S_TOT * DI];

__device__ __align__(16) float g_pe  [512 * 1536];
__device__ __align__(16) float g_xh  [S_TOT * DOUT];
__device__ __align__(16) float g_xz  [S_TOT * 1536];
__device__ __align__(16) float g_xc  [S_TOT * DI];
__device__ __align__(16) float g_xdbl[8 * L_LEN * CT];
__device__ __align__(16) float g_dts [8 * L_LEN * DI];
__device__ __align__(16) float g_ys  [8 * L_LEN * DI];
__device__ int   g_rowmap[8 * L_LEN];

// scan chunk summaries: [(g*NCHK + c) * DI + d] * NST + n
__device__ __align__(16) float g_hend  [8 * NCHK * DI * NST];
__device__ __align__(16) float g_etot  [8 * NCHK * DI * NST];
__device__ __align__(16) float g_hstart[8 * NCHK * DI * NST];

// ------------------------- helpers ------------------------------------------
__device__ __forceinline__ float block_reduce_sum(float v, float* red) {
#pragma unroll
    for (int o = 16; o > 0; o >>= 1) v += __shfl_xor_sync(0xffffffffu, v, o);
    int warp = threadIdx.x >> 5;
    if ((threadIdx.x & 31) == 0) red[warp] = v;
    __syncthreads();
    int nw = blockDim.x >> 5;
    float s = 0.f;
    for (int i = 0; i < nw; i++) s += red[i];
    __syncthreads();
    return s;
}

__device__ __forceinline__ int swap_l(int l) { return ((l & 31) << 5) | (l >> 5); }
__device__ __forceinline__ float silu_f(float v) { return v / (1.f + __expf(-v)); }

__device__ __forceinline__ void split1(float f, __nv_bfloat16* hp, __nv_bfloat16* lp) {
    __nv_bfloat16 h = __float2bfloat16(f);
    *hp = h;
    *lp = __float2bfloat16(f - __bfloat162float(h));
}
__device__ __forceinline__ void split2(float f0, float f1, unsigned& hi, unsigned& lo) {
    __nv_bfloat162 h = __floats2bfloat162_rn(f0, f1);
    float h0 = __low2float(h), h1 = __high2float(h);
    __nv_bfloat162 l = __floats2bfloat162_rn(f0 - h0, f1 - h1);
    hi = *(unsigned*)&h;
    lo = *(unsigned*)&l;
}

__device__ __forceinline__ void mma16816(float* d, const unsigned* a, const unsigned* b) {
    asm volatile(
        "mma.sync.aligned.m16n8k16.row.col.f32.bf16.bf16.f32 "
        "{%0,%1,%2,%3}, {%4,%5,%6,%7}, {%8,%9}, {%0,%1,%2,%3};"
        : "+f"(d[0]), "+f"(d[1]), "+f"(d[2]), "+f"(d[3])
        : "r"(a[0]), "r"(a[1]), "r"(a[2]), "r"(a[3]), "r"(b[0]), "r"(b[1]));
}

__device__ __forceinline__ void ldsm4(unsigned* r, unsigned addr) {
    asm volatile("ldmatrix.sync.aligned.m8n8.x4.shared.b16 {%0,%1,%2,%3}, [%4];"
                 : "=r"(r[0]), "=r"(r[1]), "=r"(r[2]), "=r"(r[3]) : "r"(addr));
}

__device__ __forceinline__ void cpa16(unsigned smem, const void* g, int srcBytes) {
    asm volatile("cp.async.cg.shared.global [%0], [%1], 16, %2;\n"
                 :: "r"(smem), "l"(g), "r"(srcBytes));
}
__device__ __forceinline__ void cpa_commit() { asm volatile("cp.async.commit_group;\n"); }
template <int N>
__device__ __forceinline__ void cpa_wait() { asm volatile("cp.async.wait_group %0;\n" :: "n"(N)); }

// ------------------------- weight conversion --------------------------------
__global__ void convert_weights(const float* __restrict__ pe_w, const float* __restrict__ lp_w,
                                const float* __restrict__ in_w, const float* __restrict__ xp_w,
                                const float* __restrict__ dt_w, const float* __restrict__ out_w)
{
    int idx = blockIdx.x * blockDim.x + threadIdx.x;
    if (idx >= W_TOT) return;
    float v;
    if      (idx < W_LP)  v = pe_w[idx - W_PE];
    else if (idx < W_IN)  v = lp_w[idx - W_LP];
    else if (idx < W_XP)  v = in_w[idx - W_IN];
    else if (idx < W_DT)  v = xp_w[idx - W_XP];
    else if (idx < W_OUT) v = dt_w[idx - W_DT];
    else                  v = out_w[idx - W_OUT];
    split1(v, &g_whi[idx], &g_wlo[idx]);
}

// ---------------- all-bf16 split tensor-core GEMM: C = A * W^T --------------
// 256 threads, 8 warps (2x4), warp tile 32x16, block tile 64x64x32, ldmatrix.
// flags: 1 = +bias[col], 2 = softplus, 4 = accumulate C, 8 = split bf16 out.
#define GBM 64
#define GBN 64
#define GBK 32
#define GSR 20   // words per smem row (16 data + 4 pad)

__global__ void gemm_bf(const __nv_bfloat16* __restrict__ Ahi, const __nv_bfloat16* __restrict__ Alo,
                        const __nv_bfloat16* __restrict__ Whi, const __nv_bfloat16* __restrict__ Wlo,
                        const float* __restrict__ bias, float* __restrict__ C,
                        __nv_bfloat16* __restrict__ SpH, __nv_bfloat16* __restrict__ SpL,
                        int M, int Ncols, int Kdim, int lda, int ldw, int ldc,
                        long aBatch, long wBatch, int wMod, long biasBatch, long cBatch,
                        const int* __restrict__ rowmap, int rmBatch, int flags)
{
    __shared__ unsigned AsH[2][GBM][GSR], AsL[2][GBM][GSR];
    __shared__ unsigned WsH[2][GBN][GSR], WsL[2][GBN][GSR];

    const int z = blockIdx.z;
    const int wz = (wMod > 1) ? (z % wMod) : 0;
    const __nv_bfloat16* AhB = Ahi + (long)z * aBatch;
    const __nv_bfloat16* AlB = Alo + (long)z * aBatch;
    const __nv_bfloat16* WhB = Whi + (long)wz * wBatch;
    const __nv_bfloat16* WlB = Wlo + (long)wz * wBatch;
    const float* biasb = bias ? (bias + (long)wz * biasBatch) : (const float*)0;
    float* Cb = C + (long)z * cBatch;
    const int* rm = rowmap ? (rowmap + (long)z * rmBatch) : (const int*)0;

    const int m0 = blockIdx.y * GBM, n0 = blockIdx.x * GBN;
    const int tid = threadIdx.x;
    const int wid = tid >> 5, lane = tid & 31;
    const int wm = (wid >> 2) * 32;      // 0 / 32
    const int wn = (wid & 3) * 16;       // 0 / 16 / 32 / 48
    const int gq = lane >> 2, qq = lane & 3;

    // loader: one 16B chunk (8 bf16) per array per thread
    const int crow = tid >> 2;
    const int ckc  = (tid & 3) * 8;
    int arow = m0 + crow;
    if (rm) arow = rm[arow];
    const __nv_bfloat16* pAh = AhB + (long)arow * lda + ckc;
    const __nv_bfloat16* pAl = AlB + (long)arow * lda + ckc;
    const int wrow = n0 + crow;
    const bool wvalid = wrow < Ncols;
    const int wr = wvalid ? wrow : 0;
    const __nv_bfloat16* pWh = WhB + (long)wr * ldw + ckc;
    const __nv_bfloat16* pWl = WlB + (long)wr * ldw + ckc;

    unsigned bAsH = (unsigned)__cvta_generic_to_shared(&AsH[0][0][0]);
    unsigned bAsL = (unsigned)__cvta_generic_to_shared(&AsL[0][0][0]);
    unsigned bWsH = (unsigned)__cvta_generic_to_shared(&WsH[0][0][0]);
    unsigned bWsL = (unsigned)__cvta_generic_to_shared(&WsL[0][0][0]);

    const unsigned ldOff = (unsigned)((crow * GSR + (ckc >> 1)) * 4);

    float acc[2][2][4];
#pragma unroll
    for (int i = 0; i < 2; i++)
#pragma unroll
        for (int j = 0; j < 2; j++)
#pragma unroll
            for (int f = 0; f < 4; f++) acc[i][j][f] = 0.f;

    const int T = (Kdim + GBK - 1) / GBK;
    const unsigned stageStride = (unsigned)(GBM * GSR * 4);

    // prologue: stage 0
    {
        int kb = (ckc + 8 <= Kdim) ? 16 : 0;
        cpa16(bAsH + ldOff, pAh, kb);
        cpa16(bAsL + ldOff, pAl, kb);
        cpa16(bWsH + ldOff, pWh, wvalid ? kb : 0);
        cpa16(bWsL + ldOff, pWl, wvalid ? kb : 0);
    }
    cpa_commit();

    // per-warp ldmatrix lane addressing
    const unsigned aRowSel = (unsigned)(lane & 15);
    const unsigned aColSel = (unsigned)((lane >> 4) * 4);
    const unsigned bRowSel = (unsigned)(((lane >> 4) << 3) + (lane & 7));
    const unsigned bColSel = (unsigned)(((lane >> 3) & 1) * 4);

    for (int t = 0; t < T; t++) {
        int s = t & 1;
        if (t + 1 < T) {
            int k0 = (t + 1) * GBK;
            unsigned so = (unsigned)((t + 1) & 1) * stageStride;
            int kb = (k0 + ckc + 8 <= Kdim) ? 16 : 0;
            cpa16(bAsH + so + ldOff, pAh + k0, kb);
            cpa16(bAsL + so + ldOff, pAl + k0, kb);
            cpa16(bWsH + so + ldOff, pWh + k0, wvalid ? kb : 0);
            cpa16(bWsL + so + ldOff, pWl + k0, wvalid ? kb : 0);
            cpa_commit();
            cpa_wait<1>();
        } else {
            cpa_wait<0>();
        }
        __syncthreads();

#pragma unroll
        for (int kk = 0; kk < 2; kk++) {
            unsigned ahi[2][4], alo[2][4], bh[4], bl[4];
            unsigned acol = (unsigned)(kk * 8) + aColSel;
#pragma unroll
            for (int i = 0; i < 2; i++) {
                unsigned ar = ((unsigned)(s * GBM + wm + i * 16) + aRowSel) * GSR + acol;
                ldsm4(ahi[i], bAsH + (ar << 2));
                ldsm4(alo[i], bAsL + (ar << 2));
            }
            {
                unsigned br = ((unsigned)(s * GBN + wn) + bRowSel) * GSR
                              + (unsigned)(kk * 8) + bColSel;
                ldsm4(bh, bWsH + (br << 2));
                ldsm4(bl, bWsL + (br << 2));
            }
#pragma unroll
            for (int i = 0; i < 2; i++)
#pragma unroll
                for (int j = 0; j < 2; j++) {
                    mma16816(acc[i][j], ahi[i], bh + j * 2);
                    mma16816(acc[i][j], ahi[i], bl + j * 2);
                    mma16816(acc[i][j], alo[i], bh + j * 2);
                }
        }
        __syncthreads();
    }

    // ------------------------------ epilogue --------------------------------
    __nv_bfloat16* SpHb = SpH ? (SpH + (long)z * cBatch) : (__nv_bfloat16*)0;
    __nv_bfloat16* SpLb = SpL ? (SpL + (long)z * cBatch) : (__nv_bfloat16*)0;
#pragma unroll
    for (int i = 0; i < 2; i++) {
        int r0 = m0 + wm + i * 16 + gq;
        int r1 = r0 + 8;
#pragma unroll
        for (int j = 0; j < 2; j++) {
            int col = n0 + wn + j * 8 + qq * 2;
            if (col >= Ncols) continue;
            float v0 = acc[i][j][0], v1 = acc[i][j][1];
            float v2 = acc[i][j][2], v3 = acc[i][j][3];
            if (flags & 1) {
                float b0 = biasb[col], b1 = biasb[col + 1];
                v0 += b0; v1 += b1; v2 += b0; v3 += b1;
            }
            if (flags & 2) {
                v0 = (v0 > 20.f) ? v0 : log1pf(__expf(v0));
                v1 = (v1 > 20.f) ? v1 : log1pf(__expf(v1));
                v2 = (v2 > 20.f) ? v2 : log1pf(__expf(v2));
                v3 = (v3 > 20.f) ? v3 : log1pf(__expf(v3));
            }
            float2* p0 = (float2*)&Cb[(long)r0 * ldc + col];
            float2* p1 = (float2*)&Cb[(long)r1 * ldc + col];
            if (flags & 4) {
                float2 o0 = *p0, o1 = *p1;
                v0 += o0.x; v1 += o0.y; v2 += o1.x; v3 += o1.y;
            }
            *p0 = make_float2(v0, v1);
            *p1 = make_float2(v2, v3);
            if (flags & 8) {
                unsigned h, l;
                split2(v0, v1, h, l);
                *(unsigned*)&SpHb[(long)r0 * ldc + col] = h;
                *(unsigned*)&SpLb[(long)r0 * ldc + col] = l;
                split2(v2, v3, h, l);
                *(unsigned*)&SpHb[(long)r1 * ldc + col] = h;
                *(unsigned*)&SpLb[(long)r1 * ldc + col] = l;
            }
        }
    }
}

// ------------------------- transposes ---------------------------------------
__global__ void transpose_split_kernel(const float* __restrict__ src,
                                       __nv_bfloat16* __restrict__ dhi,
                                       __nv_bfloat16* __restrict__ dlo,
                                       int rows, int cols)
{
    __shared__ float tile[32][33];
    int c0 = blockIdx.x * 32, r0 = blockIdx.y * 32, bz = blockIdx.z;
    const float* s = src + (long)bz * rows * cols;
    long dbase = (long)bz * rows * cols;
    for (int i = threadIdx.y; i < 32; i += 8)
        tile[i][threadIdx.x] = s[(long)(r0 + i) * cols + c0 + threadIdx.x];
    __syncthreads();
    for (int i = threadIdx.y; i < 32; i += 8) {
        long di = dbase + (long)(c0 + i) * rows + r0 + threadIdx.x;
        split1(tile[threadIdx.x][i], &dhi[di], &dlo[di]);
    }
}

__global__ void transpose_kernel(const float* __restrict__ src, float* __restrict__ dst,
                                 int rows, int cols)
{
    __shared__ float tile[32][33];
    int c0 = blockIdx.x * 32, r0 = blockIdx.y * 32, bz = blockIdx.z;
    const float* s = src + (long)bz * rows * cols;
    float* d = dst + (long)bz * rows * cols;
    for (int i = threadIdx.y; i < 32; i += 8)
        tile[i][threadIdx.x] = s[(long)(r0 + i) * cols + c0 + threadIdx.x];
    __syncthreads();
    for (int i = threadIdx.y; i < 32; i += 8)
        d[(long)(c0 + i) * rows + r0 + threadIdx.x] = tile[threadIdx.x][i];
}

// ------------------------- rowmap init --------------------------------------
__global__ void rowmap_init()
{
    int g = blockIdx.x, l = threadIdx.x;
    int k = g & 3, b = g >> 2;
    int s;
    if (k == 0) s = l;
    else if (k == 1) s = swap_l(l);
    else if (k == 2) s = 1023 - l;
    else { int m = 1023 - l; s = swap_l(m); }
    g_rowmap[g * L_LEN + l] = b * L_LEN + s;
}

// ------------------------- patch-expand LN + concat skip --------------------
__global__ void pe_cat_kernel(const float* __restrict__ pe, const float* __restrict__ skip,
                              const float* __restrict__ nw, const float* __restrict__ nb)
{
    int pix = blockIdx.x;
    int b = pix >> 10, Y = (pix >> 5) & 31, X = pix & 31;
    int h = Y >> 1, p = Y & 1, w = X >> 1, q = X & 1;
    const float* src = pe + (long)(b * 256 + h * 16 + w) * 1536 + (p * 2 + q) * 384;

    __shared__ float red[32];
    float v[3]; float ssum = 0.f;
#pragma unroll
    for (int j = 0; j < 3; j++) { v[j] = src[threadIdx.x + j * 128]; ssum += v[j]; }
    float mean = block_reduce_sum(ssum, red) * (1.f / 384.f);
    float vs = 0.f;
#pragma unroll
    for (int j = 0; j < 3; j++) { float d = v[j] - mean; vs += d * d; }
    float var = block_reduce_sum(vs, red) * (1.f / 384.f);
    float rstd = rsqrtf(var + 1e-5f);

    long dbase = (long)pix * 768;
#pragma unroll
    for (int j = 0; j < 3; j++) {
        int c = threadIdx.x + j * 128;
        split1((v[j] - mean) * rstd * nw[c] + nb[c], &g_cat_hi[dbase + c], &g_cat_lo[dbase + c]);
    }
    const float* sp = skip + (long)b * 384 * 1024 + (Y * 32 + X);
#pragma unroll
    for (int j = 0; j < 3; j++) {
        int c = threadIdx.x + j * 128;
        split1(sp[(long)c * 1024], &g_cat_hi[dbase + 384 + c], &g_cat_lo[dbase + 384 + c]);
    }
}

// ------------------------- LN over 384 (split output) ------------------------
__global__ void ln384_kernel(const float* __restrict__ in,
                             const float* __restrict__ w, const float* __restrict__ b)
{
    int row = blockIdx.x;
    const float* src = in + (long)row * 384;
    __shared__ float red[32];
    float v[3]; float ssum = 0.f;
#pragma unroll
    for (int j = 0; j < 3; j++) { v[j] = src[threadIdx.x + j * 128]; ssum += v[j]; }
    float mean = block_reduce_sum(ssum, red) * (1.f / 384.f);
    float vs = 0.f;
#pragma unroll
    for (int j = 0; j < 3; j++) { float d = v[j] - mean; vs += d * d; }
    float var = block_reduce_sum(vs, red) * (1.f / 384.f);
    float rstd = rsqrtf(var + 1e-5f);
    long dbase = (long)row * 384;
#pragma unroll
    for (int j = 0; j < 3; j++) {
        int c = threadIdx.x + j * 128;
        split1((v[j] - mean) * rstd * w[c] + b[c], &g_h_hi[dbase + c], &g_h_lo[dbase + c]);
    }
}

// ------------------------- conv + silu (fp32 + split outputs) ----------------
__global__ void conv_kernel(const float* __restrict__ xz, const float* __restrict__ cw,
                            const float* __restrict__ cb, float* __restrict__ xc)
{
    int pix = blockIdx.x;
    int b = pix >> 10, Y = (pix >> 5) & 31, X = pix & 31;
    int t = threadIdx.x;
    float acc[3] = {0.f, 0.f, 0.f};
    for (int dy = -1; dy <= 1; dy++) {
        int yy = Y + dy; if ((unsigned)yy >= 32u) continue;
        for (int dx = -1; dx <= 1; dx++) {
            int xx = X + dx; if ((unsigned)xx >= 32u) continue;
            const float* row = xz + (long)(b * 1024 + yy * 32 + xx) * 1536;
            int widx = (dy + 1) * 3 + (dx + 1);
#pragma unroll
            for (int j = 0; j < 3; j++) {
                int c = t + j * 256;
                acc[j] = fmaf(row[c], cw[c * 9 + widx], acc[j]);
            }
        }
    }
    long dbase = (long)pix * 768;
#pragma unroll
    for (int j = 0; j < 3; j++) {
        int c = t + j * 256;
        float v = silu_f(acc[j] + cb[c]);
        xc[dbase + c] = v;
        split1(v, &g_xc_hi[dbase + c], &g_xc_lo[dbase + c]);
    }
}

// ------------------------- chunked selective scan ----------------------------
__device__ __forceinline__ int scan_map(int k, int l) {
    if (k == 0) return l;
    if (k == 1) return swap_l(l);
    if (k == 2) return 1023 - l;
    return swap_l(1023 - l);
}

// pass A: thread per (g, d, chunk), 16 states in registers; local recurrence
// from h=0 and decay product E = prod(e). grid (8, 6, NCHK), block 128.
__global__ void scanA_kernel(const float* __restrict__ dts, const float* __restrict__ xc,
                             const float* __restrict__ xdbl, const float* __restrict__ A_log)
{
    int g = blockIdx.x;
    int k = g & 3, b = g >> 2;
    int d = blockIdx.y * 128 + threadIdx.x;
    int c = blockIdx.z;
    int l0 = c * CLEN;

    float A[NST], h[NST], E[NST];
    const float* al = A_log + ((long)(k * DI + d)) * NST;
#pragma unroll
    for (int n = 0; n < NST; n++) { A[n] = -__expf(al[n]); h[n] = 0.f; E[n] = 1.f; }

    const float* dtp = dts + (long)g * L_LEN * DI + d;
    const float* xdp = xdbl + (long)g * L_LEN * CT;
    const float* xcb = xc + (long)b * L_LEN * DI + d;

    for (int l = l0; l < l0 + CLEN; l++) {
        int s = scan_map(k, l);
        float dt = dtp[(long)l * DI];
        float u  = xcb[(long)s * DI];
        float dtu = dt * u;
        const float4* bc = (const float4*)(xdp + l * CT + RLOW);
        float4 B0 = bc[0], B1 = bc[1], B2 = bc[2], B3 = bc[3];
        float Bv[NST] = {B0.x, B0.y, B0.z, B0.w, B1.x, B1.y, B1.z, B1.w,
                         B2.x, B2.y, B2.z, B2.w, B3.x, B3.y, B3.z, B3.w};
#pragma unroll
        for (int n = 0; n < NST; n++) {
            float e = __expf(dt * A[n]);
            h[n] = fmaf(e, h[n], dtu * Bv[n]);
            E[n] *= e;
        }
    }
    long base = (((long)(g * NCHK + c)) * DI + d) * NST;
    float4* he = (float4*)&g_hend[base];
    float4* et = (float4*)&g_etot[base];
#pragma unroll
    for (int j = 0; j < 4; j++) {
        he[j] = make_float4(h[j * 4], h[j * 4 + 1], h[j * 4 + 2], h[j * 4 + 3]);
        et[j] = make_float4(E[j * 4], E[j * 4 + 1], E[j * 4 + 2], E[j * 4 + 3]);
    }
}

// fixup: thread per (g, d, n); sequential prefix over NCHK chunks.
// grid (8, 96), block 128 (tid = dloc*16 + n).
__global__ void scanFix_kernel()
{
    int g = blockIdx.x;
    int n = threadIdx.x & 15;
    int d = blockIdx.y * 8 + (threadIdx.x >> 4);
    float hs = 0.f;
#pragma unroll
    for (int c = 0; c < NCHK; c++) {
        long idx = (((long)(g * NCHK + c)) * DI + d) * NST + n;
        g_hstart[idx] = hs;
        hs = fmaf(g_etot[idx], hs, g_hend[idx]);
    }
}

// pass B: thread per (g, d, chunk); recompute recurrence from h_start, emit y.
__global__ void scanB_kernel(const float* __restrict__ dts, const float* __restrict__ xc,
                             const float* __restrict__ xdbl, const float* __restrict__ A_log,
                             const float* __restrict__ Ds, float* __restrict__ ys)
{
    int g = blockIdx.x;
    int k = g & 3, b = g >> 2;
    int d = blockIdx.y * 128 + threadIdx.x;
    int c = blockIdx.z;
    int l0 = c * CLEN;

    float A[NST], h[NST];
    const float* al = A_log + ((long)(k * DI + d)) * NST;
#pragma unroll
    for (int n = 0; n < NST; n++) A[n] = -__expf(al[n]);
    {
        long base = (((long)(g * NCHK + c)) * DI + d) * NST;
        const float4* hs = (const float4*)&g_hstart[base];
#pragma unroll
        for (int j = 0; j < 4; j++) {
            float4 v = hs[j];
            h[j * 4] = v.x; h[j * 4 + 1] = v.y; h[j * 4 + 2] = v.z; h[j * 4 + 3] = v.w;
        }
    }
    float Dv = Ds[k * DI + d];

    const float* dtp = dts + (long)g * L_LEN * DI + d;
    const float* xdp = xdbl + (long)g * L_LEN * CT;
    const float* xcb = xc + (long)b * L_LEN * DI + d;
    float* yp = ys + (long)g * L_LEN * DI + d;

    for (int l = l0; l < l0 + CLEN; l++) {
        int s = scan_map(k, l);
        float dt = dtp[(long)l * DI];
        float u  = xcb[(long)s * DI];
        float dtu = dt * u;
        const float4* bc = (const float4*)(xdp + l * CT + RLOW);
        float4 B0 = bc[0], B1 = bc[1], B2 = bc[2], B3 = bc[3];
        float4 C0 = bc[4], C1 = bc[5], C2 = bc[6], C3 = bc[7];
        float Bv[NST] = {B0.x, B0.y, B0.z, B0.w, B1.x, B1.y, B1.z, B1.w,
                         B2.x, B2.y, B2.z, B2.w, B3.x, B3.y, B3.z, B3.w};
        float Cv[NST] = {C0.x, C0.y, C0.z, C0.w, C1.x, C1.y, C1.z, C1.w,
                         C2.x, C2.y, C2.z, C2.w, C3.x, C3.y, C3.z, C3.w};
        float y = Dv * u;
#pragma unroll
        for (int n = 0; n < NST; n++) {
            float e = __expf(dt * A[n]);
            h[n] = fmaf(e, h[n], dtu * Bv[n]);
            y = fmaf(h[n], Cv[n], y);
        }
        yp[(long)l * DI] = y;
    }
}

// ------------------------- combine + out-LN + silu gate (split out) ----------
__global__ void combine_kernel(const float* __restrict__ ys, const float* __restrict__ xz,
                               const float* __restrict__ onw, const float* __restrict__ onb)
{
    int bs = blockIdx.x;
    int b = bs >> 10, s = bs & 1023;
    int sw = swap_l(s);
    long base0 = ((long)(b * 4 + 0) * L_LEN + s)          * DI;
    long base1 = ((long)(b * 4 + 1) * L_LEN + sw)         * DI;
    long base2 = ((long)(b * 4 + 2) * L_LEN + (1023 - s)) * DI;
    long base3 = ((long)(b * 4 + 3) * L_LEN + (1023 - sw))* DI;

    __shared__ float red[32];
    float v[3]; float ssum = 0.f;
#pragma unroll
    for (int j = 0; j < 3; j++) {
        int c = threadIdx.x + j * 256;
        v[j] = ys[base0 + c] + ys[base1 + c] + ys[base2 + c] + ys[base3 + c];
        ssum += v[j];
    }
    float mean = block_reduce_sum(ssum, red) * (1.f / 768.f);
    float vs = 0.f;
#pragma unroll
    for (int j = 0; j < 3; j++) { float d = v[j] - mean; vs += d * d; }
    float var = block_reduce_sum(vs, red) * (1.f / 768.f);
    float rstd = rsqrtf(var + 1e-5f);

    long dbase = (long)bs * DI;
#pragma unroll
    for (int j = 0; j < 3; j++) {
        int c = threadIdx.x + j * 256;
        float zz = xz[(long)bs * 1536 + 768 + c];
        float r = ((v[j] - mean) * rstd * onw[c] + onb[c]) * silu_f(zz);
        split1(r, &g_y_hi[dbase + c], &g_y_lo[dbase + c]);
    }
}

// ---------------------------------------------------------------------------
extern "C" void kernel_launch(void* const* d_in, const int* in_sizes, int n_in,
                              void* d_out, int out_size)
{
    const float* x      = (const float*)d_in[0];
    const float* skip   = (const float*)d_in[1];
    const float* pe_w   = (const float*)d_in[2];
    const float* pe_nw  = (const float*)d_in[3];
    const float* pe_nb  = (const float*)d_in[4];
    const float* lp_w   = (const float*)d_in[5];
    const float* lp_b   = (const float*)d_in[6];
    const float* bln_w  = (const float*)d_in[7];
    const float* bln_b  = (const float*)d_in[8];
    const float* in_w   = (const float*)d_in[9];
    const float* conv_w = (const float*)d_in[10];
    const float* conv_b = (const float*)d_in[11];
    const float* xp_w   = (const float*)d_in[12];
    const float* dt_w   = (const float*)d_in[13];
    const float* dt_b   = (const float*)d_in[14];
    const float* A_log  = (const float*)d_in[15];
    const float* Ds     = (const float*)d_in[16];
    const float* on_w   = (const float*)d_in[17];
    const float* on_b   = (const float*)d_in[18];
    const float* out_w  = (const float*)d_in[19];
    float* out = (float*)d_out;

    float *pe, *xh, *xz, *xc, *xdbl, *dts, *ys;
    int* rowmap;
    __nv_bfloat16 *whi, *wlo, *xTh, *xTl, *cath, *catl, *hh, *hl, *xch, *xcl, *xdh, *xdl, *yh, *yl;
    cudaGetSymbolAddress((void**)&pe,   g_pe);
    cudaGetSymbolAddress((void**)&xh,   g_xh);
    cudaGetSymbolAddress((void**)&xz,   g_xz);
    cudaGetSymbolAddress((void**)&xc,   g_xc);
    cudaGetSymbolAddress((void**)&xdbl, g_xdbl);
    cudaGetSymbolAddress((void**)&dts,  g_dts);
    cudaGetSymbolAddress((void**)&ys,   g_ys);
    cudaGetSymbolAddress((void**)&rowmap, g_rowmap);
    cudaGetSymbolAddress((void**)&whi,  g_whi);
    cudaGetSymbolAddress((void**)&wlo,  g_wlo);
    cudaGetSymbolAddress((void**)&xTh,  g_xT_hi);
    cudaGetSymbolAddress((void**)&xTl,  g_xT_lo);
    cudaGetSymbolAddress((void**)&cath, g_cat_hi);
    cudaGetSymbolAddress((void**)&catl, g_cat_lo);
    cudaGetSymbolAddress((void**)&hh,   g_h_hi);
    cudaGetSymbolAddress((void**)&hl,   g_h_lo);
    cudaGetSymbolAddress((void**)&xch,  g_xc_hi);
    cudaGetSymbolAddress((void**)&xcl,  g_xc_lo);
    cudaGetSymbolAddress((void**)&xdh,  g_xd_hi);
    cudaGetSymbolAddress((void**)&xdl,  g_xd_lo);
    cudaGetSymbolAddress((void**)&yh,   g_y_hi);
    cudaGetSymbolAddress((void**)&yl,   g_y_lo);

    convert_weights<<<(W_TOT + 255) / 256, 256>>>(pe_w, lp_w, in_w, xp_w, dt_w, out_w);
    transpose_split_kernel<<<dim3(8, 24, 2), dim3(32, 8)>>>(x, xTh, xTl, 768, 256);
    rowmap_init<<<8, 1024>>>();

    // patch-expand GEMM: (512 x 1536 x 768)
    gemm_bf<<<dim3(24, 8, 1), 256>>>(xTh, xTl, whi + W_PE, wlo + W_PE, nullptr, pe,
                                     nullptr, nullptr, 512, 1536, 768, 768, 768, 1536,
                                     0, 0, 1, 0, 0, nullptr, 0, 0);
    pe_cat_kernel<<<2048, 128>>>(pe, skip, pe_nw, pe_nb);
    // linear proj: (2048 x 384 x 768) + bias
    gemm_bf<<<dim3(6, 32, 1), 256>>>(cath, catl, whi + W_LP, wlo + W_LP, lp_b, xh,
                                     nullptr, nullptr, 2048, 384, 768, 768, 768, 384,
                                     0, 0, 1, 0, 0, nullptr, 0, 1);

    for (int layer = 0; layer < 2; layer++) {
        ln384_kernel<<<2048, 128>>>(xh, bln_w + layer * 384, bln_b + layer * 384);
        // in_proj: (2048 x 1536 x 384)
        gemm_bf<<<dim3(24, 32, 1), 256>>>(hh, hl, whi + W_IN + (long)layer * 589824,
                                          wlo + W_IN + (long)layer * 589824, nullptr, xz,
                                          nullptr, nullptr, 2048, 1536, 384, 384, 384, 1536,
                                          0, 0, 1, 0, 0, nullptr, 0, 0);
        conv_kernel<<<2048, 256>>>(xz, conv_w + (long)layer * 768 * 9,
                                   conv_b + layer * 768, xc);
        // x_proj: 8 x (1024 x 80 x 768), rowmapped A, split outputs for dt_proj
        gemm_bf<<<dim3(2, 16, 8), 256>>>(xch, xcl, whi + W_XP + (long)layer * 245760,
                                         wlo + W_XP + (long)layer * 245760, nullptr, xdbl,
                                         xdh, xdl, 1024, 80, 768, 768, 768, 80,
                                         0, 61440, 4, 0, 81920, rowmap, 1024, 8);
        // dt_proj: 8 x (1024 x 768 x 48) + bias + softplus
        gemm_bf<<<dim3(12, 16, 8), 256>>>(xdh, xdl, whi + W_DT + (long)layer * 147456,
                                          wlo + W_DT + (long)layer * 147456,
                                          dt_b + (long)layer * 3072, dts,
                                          nullptr, nullptr, 1024, 768, 48, 80, 48, 768,
                                          81920, 36864, 4, 768, 786432, nullptr, 0, 1 | 2);
        // chunked selective scan: A -> fix -> B
        scanA_kernel<<<dim3(8, 6, NCHK), 128>>>(dts, xc, xdbl,
                                                A_log + (long)layer * 4 * 768 * 16);
        scanFix_kernel<<<dim3(8, 96), 128>>>();
        scanB_kernel<<<dim3(8, 6, NCHK), 128>>>(dts, xc, xdbl,
                                                A_log + (long)layer * 4 * 768 * 16,
                                                Ds + (long)layer * 4 * 768, ys);
        combine_kernel<<<2048, 256>>>(ys, xz, on_w + layer * 768, on_b + layer * 768);
        // out_proj + residual: (2048 x 384 x 768)
        gemm_bf<<<dim3(6, 32, 1), 256>>>(yh, yl, whi + W_OUT + (long)layer * 294912,
                                         wlo + W_OUT + (long)layer * 294912, nullptr, xh,
                                         nullptr, nullptr, 2048, 384, 768, 768, 768, 384,
                                         0, 0, 1, 0, 0, nullptr, 0, 4);
    }

    transpose_kernel<<<dim3(12, 32, 2), dim3(32, 8)>>>(xh, out, 1024, 384);
}

// round 11
// speedup vs baseline: 1.6922x; 1.0264x over previous
#include <cuda_runtime.h>
#include <cuda_bf16.h>
#include <math.h>
#include <stdint.h>

// ---------------------------------------------------------------------------
// B=2, 32x32 spatial (L=1024, S=2048), out_dim=384, Di=768, N=16, R=48, K=4
// ---------------------------------------------------------------------------

#define S_TOT 2048
#define L_LEN 1024
#define DI    768
#define DOUT  384
#define NST   16
#define CT    80
#define RLOW  48
#define NCHK  16
#define CLEN  64

// weight arena offsets (elements)
#define W_PE  0
#define W_LP  1179648
#define W_IN  1474560
#define W_XP  2654208
#define W_DT  3145728
#define W_OUT 3440640
#define W_TOT 4030464

// ------------------------- scratch ------------------------------------------
__device__ __align__(16) __nv_bfloat16 g_whi[W_TOT];
__device__ __align__(16) __nv_bfloat16 g_wlo[W_TOT];

__device__ __align__(16) __nv_bfloat16 g_xT_hi[2 * 256 * 768],  g_xT_lo[2 * 256 * 768];
__device__ __align__(16) __nv_bfloat16 g_cat_hi[S_TOT * 768],   g_cat_lo[S_TOT * 768];
__device__ __align__(16) __nv_bfloat16 g_h_hi[S_TOT * DOUT],    g_h_lo[S_TOT * DOUT];
__device__ __align__(16) __nv_bfloat16 g_xc_hi[S_TOT * DI],     g_xc_lo[S_TOT * DI];
__device__ __align__(16) __nv_bfloat16 g_xd_hi[8 * L_LEN * CT], g_xd_lo[8 * L_LEN * CT];
__device__ __align__(16) __nv_bfloat16 g_y_hi[S_TOT * DI],      g_y_lo[S_TOT * DI];

__device__ __align__(16) float g_pe  [512 * 1536];
__device__ __align__(16) float g_xh  [S_TOT * DOUT];
__device__ __align__(16) float g_xz  [S_TOT * 1536];
__device__ __align__(16) float g_xc  [S_TOT * DI];
__device__ __align__(16) float g_xdbl[8 * L_LEN * CT];
__device__ __align__(16) float g_dts [8 * L_LEN * DI];
__device__ __align__(16) float g_ys  [8 * L_LEN * DI];
__device__ int   g_rowmap[8 * L_LEN];

// scan chunk summaries
__device__ __align__(16) float g_hend  [8 * NCHK * DI * NST];
__device__ __align__(16) float g_etot  [8 * NCHK * DI * NST];
__device__ __align__(16) float g_hstart[8 * NCHK * DI * NST];

// ------------------------- helpers ------------------------------------------
__device__ __forceinline__ float block_reduce_sum(float v, float* red) {
#pragma unroll
    for (int o = 16; o > 0; o >>= 1) v += __shfl_xor_sync(0xffffffffu, v, o);
    int warp = threadIdx.x >> 5;
    if ((threadIdx.x & 31) == 0) red[warp] = v;
    __syncthreads();
    int nw = blockDim.x >> 5;
    float s = 0.f;
    for (int i = 0; i < nw; i++) s += red[i];
    __syncthreads();
    return s;
}

__device__ __forceinline__ int swap_l(int l) { return ((l & 31) << 5) | (l >> 5); }
__device__ __forceinline__ float silu_f(float v) { return v / (1.f + __expf(-v)); }

__device__ __forceinline__ void split1(float f, __nv_bfloat16* hp, __nv_bfloat16* lp) {
    __nv_bfloat16 h = __float2bfloat16(f);
    *hp = h;
    *lp = __float2bfloat16(f - __bfloat162float(h));
}
__device__ __forceinline__ void split2(float f0, float f1, unsigned& hi, unsigned& lo) {
    __nv_bfloat162 h = __floats2bfloat162_rn(f0, f1);
    float h0 = __low2float(h), h1 = __high2float(h);
    __nv_bfloat162 l = __floats2bfloat162_rn(f0 - h0, f1 - h1);
    hi = *(unsigned*)&h;
    lo = *(unsigned*)&l;
}

__device__ __forceinline__ void mma16816(float* d, const unsigned* a, const unsigned* b) {
    asm volatile(
        "mma.sync.aligned.m16n8k16.row.col.f32.bf16.bf16.f32 "
        "{%0,%1,%2,%3}, {%4,%5,%6,%7}, {%8,%9}, {%0,%1,%2,%3};"
        : "+f"(d[0]), "+f"(d[1]), "+f"(d[2]), "+f"(d[3])
        : "r"(a[0]), "r"(a[1]), "r"(a[2]), "r"(a[3]), "r"(b[0]), "r"(b[1]));
}

__device__ __forceinline__ void ldsm4(unsigned* r, unsigned addr) {
    asm volatile("ldmatrix.sync.aligned.m8n8.x4.shared.b16 {%0,%1,%2,%3}, [%4];"
                 : "=r"(r[0]), "=r"(r[1]), "=r"(r[2]), "=r"(r[3]) : "r"(addr));
}

__device__ __forceinline__ void cpa16(unsigned smem, const void* g, int srcBytes) {
    asm volatile("cp.async.cg.shared.global [%0], [%1], 16, %2;\n"
                 :: "r"(smem), "l"(g), "r"(srcBytes));
}
__device__ __forceinline__ void cpa_commit() { asm volatile("cp.async.commit_group;\n"); }
template <int N>
__device__ __forceinline__ void cpa_wait() { asm volatile("cp.async.wait_group %0;\n" :: "n"(N)); }

// ------------------------- small utility kernels -----------------------------
__global__ void zero2_kernel(float* a, int na4, float* b, int nb4)
{
    int i = blockIdx.x * blockDim.x + threadIdx.x;
    float4 z = make_float4(0.f, 0.f, 0.f, 0.f);
    if (i < na4) ((float4*)a)[i] = z;
    if (i < nb4) ((float4*)b)[i] = z;
}

__global__ void zero1_kernel(float* a, int na4)
{
    int i = blockIdx.x * blockDim.x + threadIdx.x;
    if (i < na4) ((float4*)a)[i] = make_float4(0.f, 0.f, 0.f, 0.f);
}

__global__ void split_xdbl_kernel()
{
    int i = blockIdx.x * blockDim.x + threadIdx.x;
    if (i < 8 * L_LEN * CT) split1(g_xdbl[i], &g_xd_hi[i], &g_xd_lo[i]);
}

// ------------------------- weight conversion --------------------------------
__global__ void convert_weights(const float* __restrict__ pe_w, const float* __restrict__ lp_w,
                                const float* __restrict__ in_w, const float* __restrict__ xp_w,
                                const float* __restrict__ dt_w, const float* __restrict__ out_w)
{
    int idx = blockIdx.x * blockDim.x + threadIdx.x;
    if (idx >= W_TOT) return;
    float v;
    if      (idx < W_LP)  v = pe_w[idx - W_PE];
    else if (idx < W_IN)  v = lp_w[idx - W_LP];
    else if (idx < W_XP)  v = in_w[idx - W_IN];
    else if (idx < W_DT)  v = xp_w[idx - W_XP];
    else if (idx < W_OUT) v = dt_w[idx - W_DT];
    else                  v = out_w[idx - W_OUT];
    split1(v, &g_whi[idx], &g_wlo[idx]);
}

// ---------------- all-bf16 split tensor-core GEMM: C = A * W^T --------------
// 256 threads, 8 warps (2x4), warp tile 32x16, block tile 64x64x32, ldmatrix.
// flags: 1 = +bias[col], 2 = softplus, 4 = accumulate C, 8 = split bf16 out.
// splitK > 1: blockIdx.z = z*splitK + ks; each split covers T/splitK k-tiles
// and atomicAdds into C (bias only from ks==0; flags 2/8 unsupported there).
#define GBM 64
#define GBN 64
#define GBK 32
#define GSR 20   // words per smem row (16 data + 4 pad)

__global__ void gemm_bf(const __nv_bfloat16* __restrict__ Ahi, const __nv_bfloat16* __restrict__ Alo,
                        const __nv_bfloat16* __restrict__ Whi, const __nv_bfloat16* __restrict__ Wlo,
                        const float* __restrict__ bias, float* __restrict__ C,
                        __nv_bfloat16* __restrict__ SpH, __nv_bfloat16* __restrict__ SpL,
                        int M, int Ncols, int Kdim, int lda, int ldw, int ldc,
                        long aBatch, long wBatch, int wMod, long biasBatch, long cBatch,
                        const int* __restrict__ rowmap, int rmBatch, int flags, int splitK)
{
    __shared__ unsigned AsH[2][GBM][GSR], AsL[2][GBM][GSR];
    __shared__ unsigned WsH[2][GBN][GSR], WsL[2][GBN][GSR];

    int zRaw = blockIdx.z;
    int ks = 0;
    if (splitK > 1) { ks = zRaw % splitK; zRaw /= splitK; }
    const int z = zRaw;
    const int wz = (wMod > 1) ? (z % wMod) : 0;
    const __nv_bfloat16* AhB = Ahi + (long)z * aBatch;
    const __nv_bfloat16* AlB = Alo + (long)z * aBatch;
    const __nv_bfloat16* WhB = Whi + (long)wz * wBatch;
    const __nv_bfloat16* WlB = Wlo + (long)wz * wBatch;
    const float* biasb = bias ? (bias + (long)wz * biasBatch) : (const float*)0;
    float* Cb = C + (long)z * cBatch;
    const int* rm = rowmap ? (rowmap + (long)z * rmBatch) : (const int*)0;

    const int m0 = blockIdx.y * GBM, n0 = blockIdx.x * GBN;
    const int tid = threadIdx.x;
    const int wid = tid >> 5, lane = tid & 31;
    const int wm = (wid >> 2) * 32;
    const int wn = (wid & 3) * 16;
    const int gq = lane >> 2, qq = lane & 3;

    // loader: one 16B chunk (8 bf16) per array per thread
    const int crow = tid >> 2;
    const int ckc  = (tid & 3) * 8;
    int arow = m0 + crow;
    if (rm) arow = rm[arow];
    const __nv_bfloat16* pAh = AhB + (long)arow * lda + ckc;
    const __nv_bfloat16* pAl = AlB + (long)arow * lda + ckc;
    const int wrow = n0 + crow;
    const bool wvalid = wrow < Ncols;
    const int wr = wvalid ? wrow : 0;
    const __nv_bfloat16* pWh = WhB + (long)wr * ldw + ckc;
    const __nv_bfloat16* pWl = WlB + (long)wr * ldw + ckc;

    unsigned bAsH = (unsigned)__cvta_generic_to_shared(&AsH[0][0][0]);
    unsigned bAsL = (unsigned)__cvta_generic_to_shared(&AsL[0][0][0]);
    unsigned bWsH = (unsigned)__cvta_generic_to_shared(&WsH[0][0][0]);
    unsigned bWsL = (unsigned)__cvta_generic_to_shared(&WsL[0][0][0]);

    const unsigned ldOff = (unsigned)((crow * GSR + (ckc >> 1)) * 4);

    float acc[2][2][4];
#pragma unroll
    for (int i = 0; i < 2; i++)
#pragma unroll
        for (int j = 0; j < 2; j++)
#pragma unroll
            for (int f = 0; f < 4; f++) acc[i][j][f] = 0.f;

    const int T = (Kdim + GBK - 1) / GBK;
    const int TP = T / (splitK > 1 ? splitK : 1);
    const int t0 = ks * TP;
    const int t1 = (splitK > 1) ? (t0 + TP) : T;
    const unsigned stageStride = (unsigned)(GBM * GSR * 4);

    // prologue: stage for tile t0
    {
        int k0 = t0 * GBK;
        int kb = (k0 + ckc + 8 <= Kdim) ? 16 : 0;
        cpa16(bAsH + ldOff, pAh + k0, kb);
        cpa16(bAsL + ldOff, pAl + k0, kb);
        cpa16(bWsH + ldOff, pWh + k0, wvalid ? kb : 0);
        cpa16(bWsL + ldOff, pWl + k0, wvalid ? kb : 0);
    }
    cpa_commit();

    const unsigned aRowSel = (unsigned)(lane & 15);
    const unsigned aColSel = (unsigned)((lane >> 4) * 4);
    const unsigned bRowSel = (unsigned)(((lane >> 4) << 3) + (lane & 7));
    const unsigned bColSel = (unsigned)(((lane >> 3) & 1) * 4);

    for (int t = t0; t < t1; t++) {
        int s = (t - t0) & 1;
        if (t + 1 < t1) {
            int k0 = (t + 1) * GBK;
            unsigned so = (unsigned)((t + 1 - t0) & 1) * stageStride;
            int kb = (k0 + ckc + 8 <= Kdim) ? 16 : 0;
            cpa16(bAsH + so + ldOff, pAh + k0, kb);
            cpa16(bAsL + so + ldOff, pAl + k0, kb);
            cpa16(bWsH + so + ldOff, pWh + k0, wvalid ? kb : 0);
            cpa16(bWsL + so + ldOff, pWl + k0, wvalid ? kb : 0);
            cpa_commit();
            cpa_wait<1>();
        } else {
            cpa_wait<0>();
        }
        __syncthreads();

#pragma unroll
        for (int kk = 0; kk < 2; kk++) {
            unsigned ahi[2][4], alo[2][4], bh[4], bl[4];
            unsigned acol = (unsigned)(kk * 8) + aColSel;
#pragma unroll
            for (int i = 0; i < 2; i++) {
                unsigned ar = ((unsigned)(s * GBM + wm + i * 16) + aRowSel) * GSR + acol;
                ldsm4(ahi[i], bAsH + (ar << 2));
                ldsm4(alo[i], bAsL + (ar << 2));
            }
            {
                unsigned br = ((unsigned)(s * GBN + wn) + bRowSel) * GSR
                              + (unsigned)(kk * 8) + bColSel;
                ldsm4(bh, bWsH + (br << 2));
                ldsm4(bl, bWsL + (br << 2));
            }
#pragma unroll
            for (int i = 0; i < 2; i++)
#pragma unroll
                for (int j = 0; j < 2; j++) {
                    mma16816(acc[i][j], ahi[i], bh + j * 2);
                    mma16816(acc[i][j], ahi[i], bl + j * 2);
                    mma16816(acc[i][j], alo[i], bh + j * 2);
                }
        }
        __syncthreads();
    }

    // ------------------------------ epilogue --------------------------------
    if (splitK > 1) {
        // atomic accumulate; bias applied only by split 0
#pragma unroll
        for (int i = 0; i < 2; i++) {
            int r0 = m0 + wm + i * 16 + gq;
            int r1 = r0 + 8;
#pragma unroll
            for (int j = 0; j < 2; j++) {
                int col = n0 + wn + j * 8 + qq * 2;
                if (col >= Ncols) continue;
                float v0 = acc[i][j][0], v1 = acc[i][j][1];
                float v2 = acc[i][j][2], v3 = acc[i][j][3];
                if ((flags & 1) && ks == 0) {
                    float b0 = biasb[col], b1 = biasb[col + 1];
                    v0 += b0; v1 += b1; v2 += b0; v3 += b1;
                }
                atomicAdd(&Cb[(long)r0 * ldc + col], v0);
                atomicAdd(&Cb[(long)r0 * ldc + col + 1], v1);
                atomicAdd(&Cb[(long)r1 * ldc + col], v2);
                atomicAdd(&Cb[(long)r1 * ldc + col + 1], v3);
            }
        }
        return;
    }

    __nv_bfloat16* SpHb = SpH ? (SpH + (long)z * cBatch) : (__nv_bfloat16*)0;
    __nv_bfloat16* SpLb = SpL ? (SpL + (long)z * cBatch) : (__nv_bfloat16*)0;
#pragma unroll
    for (int i = 0; i < 2; i++) {
        int r0 = m0 + wm + i * 16 + gq;
        int r1 = r0 + 8;
#pragma unroll
        for (int j = 0; j < 2; j++) {
            int col = n0 + wn + j * 8 + qq * 2;
            if (col >= Ncols) continue;
            float v0 = acc[i][j][0], v1 = acc[i][j][1];
            float v2 = acc[i][j][2], v3 = acc[i][j][3];
            if (flags & 1) {
                float b0 = biasb[col], b1 = biasb[col + 1];
                v0 += b0; v1 += b1; v2 += b0; v3 += b1;
            }
            if (flags & 2) {
                v0 = (v0 > 20.f) ? v0 : log1pf(__expf(v0));
                v1 = (v1 > 20.f) ? v1 : log1pf(__expf(v1));
                v2 = (v2 > 20.f) ? v2 : log1pf(__expf(v2));
                v3 = (v3 > 20.f) ? v3 : log1pf(__expf(v3));
            }
            float2* p0 = (float2*)&Cb[(long)r0 * ldc + col];
            float2* p1 = (float2*)&Cb[(long)r1 * ldc + col];
            if (flags & 4) {
                float2 o0 = *p0, o1 = *p1;
                v0 += o0.x; v1 += o0.y; v2 += o1.x; v3 += o1.y;
            }
            *p0 = make_float2(v0, v1);
            *p1 = make_float2(v2, v3);
            if (flags & 8) {
                unsigned h, l;
                split2(v0, v1, h, l);
                *(unsigned*)&SpHb[(long)r0 * ldc + col] = h;
                *(unsigned*)&SpLb[(long)r0 * ldc + col] = l;
                split2(v2, v3, h, l);
                *(unsigned*)&SpHb[(long)r1 * ldc + col] = h;
                *(unsigned*)&SpLb[(long)r1 * ldc + col] = l;
            }
        }
    }
}

// ------------------------- transposes ---------------------------------------
__global__ void transpose_split_kernel(const float* __restrict__ src,
                                       __nv_bfloat16* __restrict__ dhi,
                                       __nv_bfloat16* __restrict__ dlo,
                                       int rows, int cols)
{
    __shared__ float tile[32][33];
    int c0 = blockIdx.x * 32, r0 = blockIdx.y * 32, bz = blockIdx.z;
    const float* s = src + (long)bz * rows * cols;
    long dbase = (long)bz * rows * cols;
    for (int i = threadIdx.y; i < 32; i += 8)
        tile[i][threadIdx.x] = s[(long)(r0 + i) * cols + c0 + threadIdx.x];
    __syncthreads();
    for (int i = threadIdx.y; i < 32; i += 8) {
        long di = dbase + (long)(c0 + i) * rows + r0 + threadIdx.x;
        split1(tile[threadIdx.x][i], &dhi[di], &dlo[di]);
    }
}

__global__ void transpose_kernel(const float* __restrict__ src, float* __restrict__ dst,
                                 int rows, int cols)
{
    __shared__ float tile[32][33];
    int c0 = blockIdx.x * 32, r0 = blockIdx.y * 32, bz = blockIdx.z;
    const float* s = src + (long)bz * rows * cols;
    float* d = dst + (long)bz * rows * cols;
    for (int i = threadIdx.y; i < 32; i += 8)
        tile[i][threadIdx.x] = s[(long)(r0 + i) * cols + c0 + threadIdx.x];
    __syncthreads();
    for (int i = threadIdx.y; i < 32; i += 8)
        d[(long)(c0 + i) * rows + r0 + threadIdx.x] = tile[threadIdx.x][i];
}

// ------------------------- rowmap init --------------------------------------
__global__ void rowmap_init()
{
    int g = blockIdx.x, l = threadIdx.x;
    int k = g & 3, b = g >> 2;
    int s;
    if (k == 0) s = l;
    else if (k == 1) s = swap_l(l);
    else if (k == 2) s = 1023 - l;
    else { int m = 1023 - l; s = swap_l(m); }
    g_rowmap[g * L_LEN + l] = b * L_LEN + s;
}

// ------------------------- patch-expand LN + concat skip --------------------
__global__ void pe_cat_kernel(const float* __restrict__ pe, const float* __restrict__ skip,
                              const float* __restrict__ nw, const float* __restrict__ nb)
{
    int pix = blockIdx.x;
    int b = pix >> 10, Y = (pix >> 5) & 31, X = pix & 31;
    int h = Y >> 1, p = Y & 1, w = X >> 1, q = X & 1;
    const float* src = pe + (long)(b * 256 + h * 16 + w) * 1536 + (p * 2 + q) * 384;

    __shared__ float red[32];
    float v[3]; float ssum = 0.f;
#pragma unroll
    for (int j = 0; j < 3; j++) { v[j] = src[threadIdx.x + j * 128]; ssum += v[j]; }
    float mean = block_reduce_sum(ssum, red) * (1.f / 384.f);
    float vs = 0.f;
#pragma unroll
    for (int j = 0; j < 3; j++) { float d = v[j] - mean; vs += d * d; }
    float var = block_reduce_sum(vs, red) * (1.f / 384.f);
    float rstd = rsqrtf(var + 1e-5f);

    long dbase = (long)pix * 768;
#pragma unroll
    for (int j = 0; j < 3; j++) {
        int c = threadIdx.x + j * 128;
        split1((v[j] - mean) * rstd * nw[c] + nb[c], &g_cat_hi[dbase + c], &g_cat_lo[dbase + c]);
    }
    const float* sp = skip + (long)b * 384 * 1024 + (Y * 32 + X);
#pragma unroll
    for (int j = 0; j < 3; j++) {
        int c = threadIdx.x + j * 128;
        split1(sp[(long)c * 1024], &g_cat_hi[dbase + 384 + c], &g_cat_lo[dbase + 384 + c]);
    }
}

// ------------------------- LN over 384 (split output) ------------------------
__global__ void ln384_kernel(const float* __restrict__ in,
                             const float* __restrict__ w, const float* __restrict__ b)
{
    int row = blockIdx.x;
    const float* src = in + (long)row * 384;
    __shared__ float red[32];
    float v[3]; float ssum = 0.f;
#pragma unroll
    for (int j = 0; j < 3; j++) { v[j] = src[threadIdx.x + j * 128]; ssum += v[j]; }
    float mean = block_reduce_sum(ssum, red) * (1.f / 384.f);
    float vs = 0.f;
#pragma unroll
    for (int j = 0; j < 3; j++) { float d = v[j] - mean; vs += d * d; }
    float var = block_reduce_sum(vs, red) * (1.f / 384.f);
    float rstd = rsqrtf(var + 1e-5f);
    long dbase = (long)row * 384;
#pragma unroll
    for (int j = 0; j < 3; j++) {
        int c = threadIdx.x + j * 128;
        split1((v[j] - mean) * rstd * w[c] + b[c], &g_h_hi[dbase + c], &g_h_lo[dbase + c]);
    }
}

// ------------------------- conv + silu (fp32 + split outputs) ----------------
__global__ void conv_kernel(const float* __restrict__ xz, const float* __restrict__ cw,
                            const float* __restrict__ cb, float* __restrict__ xc)
{
    int pix = blockIdx.x;
    int b = pix >> 10, Y = (pix >> 5) & 31, X = pix & 31;
    int t = threadIdx.x;
    float acc[3] = {0.f, 0.f, 0.f};
    for (int dy = -1; dy <= 1; dy++) {
        int yy = Y + dy; if ((unsigned)yy >= 32u) continue;
        for (int dx = -1; dx <= 1; dx++) {
            int xx = X + dx; if ((unsigned)xx >= 32u) continue;
            const float* row = xz + (long)(b * 1024 + yy * 32 + xx) * 1536;
            int widx = (dy + 1) * 3 + (dx + 1);
#pragma unroll
            for (int j = 0; j < 3; j++) {
                int c = t + j * 256;
                acc[j] = fmaf(row[c], cw[c * 9 + widx], acc[j]);
            }
        }
    }
    long dbase = (long)pix * 768;
#pragma unroll
    for (int j = 0; j < 3; j++) {
        int c = t + j * 256;
        float v = silu_f(acc[j] + cb[c]);
        xc[dbase + c] = v;
        split1(v, &g_xc_hi[dbase + c], &g_xc_lo[dbase + c]);
    }
}

// ------------------------- chunked selective scan ----------------------------
__device__ __forceinline__ int scan_map(int k, int l) {
    if (k == 0) return l;
    if (k == 1) return swap_l(l);
    if (k == 2) return 1023 - l;
    return swap_l(1023 - l);
}

__global__ void scanA_kernel(const float* __restrict__ dts, const float* __restrict__ xc,
                             const float* __restrict__ xdbl, const float* __restrict__ A_log)
{
    int g = blockIdx.x;
    int k = g & 3, b = g >> 2;
    int d = blockIdx.y * 128 + threadIdx.x;
    int c = blockIdx.z;
    int l0 = c * CLEN;

    float A[NST], h[NST], E[NST];
    const float* al = A_log + ((long)(k * DI + d)) * NST;
#pragma unroll
    for (int n = 0; n < NST; n++) { A[n] = -__expf(al[n]); h[n] = 0.f; E[n] = 1.f; }

    const float* dtp = dts + (long)g * L_LEN * DI + d;
    const float* xdp = xdbl + (long)g * L_LEN * CT;
    const float* xcb = xc + (long)b * L_LEN * DI + d;

    for (int l = l0; l < l0 + CLEN; l++) {
        int s = scan_map(k, l);
        float dt = dtp[(long)l * DI];
        float u  = xcb[(long)s * DI];
        float dtu = dt * u;
        const float4* bc = (const float4*)(xdp + l * CT + RLOW);
        float4 B0 = bc[0], B1 = bc[1], B2 = bc[2], B3 = bc[3];
        float Bv[NST] = {B0.x, B0.y, B0.z, B0.w, B1.x, B1.y, B1.z, B1.w,
                         B2.x, B2.y, B2.z, B2.w, B3.x, B3.y, B3.z, B3.w};
#pragma unroll
        for (int n = 0; n < NST; n++) {
            float e = __expf(dt * A[n]);
            h[n] = fmaf(e, h[n], dtu * Bv[n]);
            E[n] *= e;
        }
    }
    long base = (((long)(g * NCHK + c)) * DI + d) * NST;
    float4* he = (float4*)&g_hend[base];
    float4* et = (float4*)&g_etot[base];
#pragma unroll
    for (int j = 0; j < 4; j++) {
        he[j] = make_float4(h[j * 4], h[j * 4 + 1], h[j * 4 + 2], h[j * 4 + 3]);
        et[j] = make_float4(E[j * 4], E[j * 4 + 1], E[j * 4 + 2], E[j * 4 + 3]);
    }
}

__global__ void scanFix_kernel()
{
    int g = blockIdx.x;
    int n = threadIdx.x & 15;
    int d = blockIdx.y * 8 + (threadIdx.x >> 4);
    float hs = 0.f;
#pragma unroll
    for (int c = 0; c < NCHK; c++) {
        long idx = (((long)(g * NCHK + c)) * DI + d) * NST + n;
        g_hstart[idx] = hs;
        hs = fmaf(g_etot[idx], hs, g_hend[idx]);
    }
}

__global__ void scanB_kernel(const float* __restrict__ dts, const float* __restrict__ xc,
                             const float* __restrict__ xdbl, const float* __restrict__ A_log,
                             const float* __restrict__ Ds, float* __restrict__ ys)
{
    int g = blockIdx.x;
    int k = g & 3, b = g >> 2;
    int d = blockIdx.y * 128 + threadIdx.x;
    int c = blockIdx.z;
    int l0 = c * CLEN;

    float A[NST], h[NST];
    const float* al = A_log + ((long)(k * DI + d)) * NST;
#pragma unroll
    for (int n = 0; n < NST; n++) A[n] = -__expf(al[n]);
    {
        long base = (((long)(g * NCHK + c)) * DI + d) * NST;
        const float4* hs = (const float4*)&g_hstart[base];
#pragma unroll
        for (int j = 0; j < 4; j++) {
            float4 v = hs[j];
            h[j * 4] = v.x; h[j * 4 + 1] = v.y; h[j * 4 + 2] = v.z; h[j * 4 + 3] = v.w;
        }
    }
    float Dv = Ds[k * DI + d];

    const float* dtp = dts + (long)g * L_LEN * DI + d;
    const float* xdp = xdbl + (long)g * L_LEN * CT;
    const float* xcb = xc + (long)b * L_LEN * DI + d;
    float* yp = ys + (long)g * L_LEN * DI + d;

    for (int l = l0; l < l0 + CLEN; l++) {
        int s = scan_map(k, l);
        float dt = dtp[(long)l * DI];
        float u  = xcb[(long)s * DI];
        float dtu = dt * u;
        const float4* bc = (const float4*)(xdp + l * CT + RLOW);
        float4 B0 = bc[0], B1 = bc[1], B2 = bc[2], B3 = bc[3];
        float4 C0 = bc[4], C1 = bc[5], C2 = bc[6], C3 = bc[7];
        float Bv[NST] = {B0.x, B0.y, B0.z, B0.w, B1.x, B1.y, B1.z, B1.w,
                         B2.x, B2.y, B2.z, B2.w, B3.x, B3.y, B3.z, B3.w};
        float Cv[NST] = {C0.x, C0.y, C0.z, C0.w, C1.x, C1.y, C1.z, C1.w,
                         C2.x, C2.y, C2.z, C2.w, C3.x, C3.y, C3.z, C3.w};
        float y = Dv * u;
#pragma unroll
        for (int n = 0; n < NST; n++) {
            float e = __expf(dt * A[n]);
            h[n] = fmaf(e, h[n], dtu * Bv[n]);
            y = fmaf(h[n], Cv[n], y);
        }
        yp[(long)l * DI] = y;
    }
}

// ------------------------- combine + out-LN + silu gate (split out) ----------
__global__ void combine_kernel(const float* __restrict__ ys, const float* __restrict__ xz,
                               const float* __restrict__ onw, const float* __restrict__ onb)
{
    int bs = blockIdx.x;
    int b = bs >> 10, s = bs & 1023;
    int sw = swap_l(s);
    long base0 = ((long)(b * 4 + 0) * L_LEN + s)          * DI;
    long base1 = ((long)(b * 4 + 1) * L_LEN + sw)         * DI;
    long base2 = ((long)(b * 4 + 2) * L_LEN + (1023 - s)) * DI;
    long base3 = ((long)(b * 4 + 3) * L_LEN + (1023 - sw))* DI;

    __shared__ float red[32];
    float v[3]; float ssum = 0.f;
#pragma unroll
    for (int j = 0; j < 3; j++) {
        int c = threadIdx.x + j * 256;
        v[j] = ys[base0 + c] + ys[base1 + c] + ys[base2 + c] + ys[base3 + c];
        ssum += v[j];
    }
    float mean = block_reduce_sum(ssum, red) * (1.f / 768.f);
    float vs = 0.f;
#pragma unroll
    for (int j = 0; j < 3; j++) { float d = v[j] - mean; vs += d * d; }
    float var = block_reduce_sum(vs, red) * (1.f / 768.f);
    float rstd = rsqrtf(var + 1e-5f);

    long dbase = (long)bs * DI;
#pragma unroll
    for (int j = 0; j < 3; j++) {
        int c = threadIdx.x + j * 256;
        float zz = xz[(long)bs * 1536 + 768 + c];
        float r = ((v[j] - mean) * rstd * onw[c] + onb[c]) * silu_f(zz);
        split1(r, &g_y_hi[dbase + c], &g_y_lo[dbase + c]);
    }
}

// ---------------------------------------------------------------------------
extern "C" void kernel_launch(void* const* d_in, const int* in_sizes, int n_in,
                              void* d_out, int out_size)
{
    const float* x      = (const float*)d_in[0];
    const float* skip   = (const float*)d_in[1];
    const float* pe_w   = (const float*)d_in[2];
    const float* pe_nw  = (const float*)d_in[3];
    const float* pe_nb  = (const float*)d_in[4];
    const float* lp_w   = (const float*)d_in[5];
    const float* lp_b   = (const float*)d_in[6];
    const float* bln_w  = (const float*)d_in[7];
    const float* bln_b  = (const float*)d_in[8];
    const float* in_w   = (const float*)d_in[9];
    const float* conv_w = (const float*)d_in[10];
    const float* conv_b = (const float*)d_in[11];
    const float* xp_w   = (const float*)d_in[12];
    const float* dt_w   = (const float*)d_in[13];
    const float* dt_b   = (const float*)d_in[14];
    const float* A_log  = (const float*)d_in[15];
    const float* Ds     = (const float*)d_in[16];
    const float* on_w   = (const float*)d_in[17];
    const float* on_b   = (const float*)d_in[18];
    const float* out_w  = (const float*)d_in[19];
    float* out = (float*)d_out;

    float *pe, *xh, *xz, *xc, *xdbl, *dts, *ys;
    int* rowmap;
    __nv_bfloat16 *whi, *wlo, *xTh, *xTl, *cath, *catl, *hh, *hl, *xch, *xcl, *xdh, *xdl, *yh, *yl;
    cudaGetSymbolAddress((void**)&pe,   g_pe);
    cudaGetSymbolAddress((void**)&xh,   g_xh);
    cudaGetSymbolAddress((void**)&xz,   g_xz);
    cudaGetSymbolAddress((void**)&xc,   g_xc);
    cudaGetSymbolAddress((void**)&xdbl, g_xdbl);
    cudaGetSymbolAddress((void**)&dts,  g_dts);
    cudaGetSymbolAddress((void**)&ys,   g_ys);
    cudaGetSymbolAddress((void**)&rowmap, g_rowmap);
    cudaGetSymbolAddress((void**)&whi,  g_whi);
    cudaGetSymbolAddress((void**)&wlo,  g_wlo);
    cudaGetSymbolAddress((void**)&xTh,  g_xT_hi);
    cudaGetSymbolAddress((void**)&xTl,  g_xT_lo);
    cudaGetSymbolAddress((void**)&cath, g_cat_hi);
    cudaGetSymbolAddress((void**)&catl, g_cat_lo);
    cudaGetSymbolAddress((void**)&hh,   g_h_hi);
    cudaGetSymbolAddress((void**)&hl,   g_h_lo);
    cudaGetSymbolAddress((void**)&xch,  g_xc_hi);
    cudaGetSymbolAddress((void**)&xcl,  g_xc_lo);
    cudaGetSymbolAddress((void**)&xdh,  g_xd_hi);
    cudaGetSymbolAddress((void**)&xdl,  g_xd_lo);
    cudaGetSymbolAddress((void**)&yh,   g_y_hi);
    cudaGetSymbolAddress((void**)&yl,   g_y_lo);

    convert_weights<<<(W_TOT + 255) / 256, 256>>>(pe_w, lp_w, in_w, xp_w, dt_w, out_w);
    transpose_split_kernel<<<dim3(8, 24, 2), dim3(32, 8)>>>(x, xTh, xTl, 768, 256);
    rowmap_init<<<8, 1024>>>();
    // zero split-K accumulation targets: pe (786432) and xh (786432)
    zero2_kernel<<<(196608 + 255) / 256, 256>>>(pe, 196608, xh, 196608);

    // patch-expand GEMM: (512 x 1536 x 768), split-K x4 -> 768 blocks
    gemm_bf<<<dim3(24, 8, 4), 256>>>(xTh, xTl, whi + W_PE, wlo + W_PE, nullptr, pe,
                                     nullptr, nullptr, 512, 1536, 768, 768, 768, 1536,
                                     0, 0, 1, 0, 0, nullptr, 0, 0, 4);
    pe_cat_kernel<<<2048, 128>>>(pe, skip, pe_nw, pe_nb);
    // linear proj: (2048 x 384 x 768) + bias, split-K x4 -> 768 blocks
    gemm_bf<<<dim3(6, 32, 4), 256>>>(cath, catl, whi + W_LP, wlo + W_LP, lp_b, xh,
                                     nullptr, nullptr, 2048, 384, 768, 768, 768, 384,
                                     0, 0, 1, 0, 0, nullptr, 0, 1, 4);

    for (int layer = 0; layer < 2; layer++) {
        ln384_kernel<<<2048, 128>>>(xh, bln_w + layer * 384, bln_b + layer * 384);
        // in_proj: (2048 x 1536 x 384), 768 blocks (no split-K needed)
        gemm_bf<<<dim3(24, 32, 1), 256>>>(hh, hl, whi + W_IN + (long)layer * 589824,
                                          wlo + W_IN + (long)layer * 589824, nullptr, xz,
                                          nullptr, nullptr, 2048, 1536, 384, 384, 384, 1536,
                                          0, 0, 1, 0, 0, nullptr, 0, 0, 1);
        conv_kernel<<<2048, 256>>>(xz, conv_w + (long)layer * 768 * 9,
                                   conv_b + layer * 768, xc);
        // x_proj: 8 x (1024 x 80 x 768), split-K x4 -> 1024 blocks (zero first)
        zero1_kernel<<<(163840 + 255) / 256, 256>>>(xdbl, 163840);
        gemm_bf<<<dim3(2, 16, 32), 256>>>(xch, xcl, whi + W_XP + (long)layer * 245760,
                                          wlo + W_XP + (long)layer * 245760, nullptr, xdbl,
                                          nullptr, nullptr, 1024, 80, 768, 768, 768, 80,
                                          0, 61440, 4, 0, 81920, rowmap, 1024, 0, 4);
        split_xdbl_kernel<<<(8 * L_LEN * CT + 255) / 256, 256>>>();
        // dt_proj: 8 x (1024 x 768 x 48) + bias + softplus, 1536 blocks
        gemm_bf<<<dim3(12, 16, 8), 256>>>(xdh, xdl, whi + W_DT + (long)layer * 147456,
                                          wlo + W_DT + (long)layer * 147456,
                                          dt_b + (long)layer * 3072, dts,
                                          nullptr, nullptr, 1024, 768, 48, 80, 48, 768,
                                          81920, 36864, 4, 768, 786432, nullptr, 0, 1 | 2, 1);
        // chunked selective scan: A -> fix -> B
        scanA_kernel<<<dim3(8, 6, NCHK), 128>>>(dts, xc, xdbl,
                                                A_log + (long)layer * 4 * 768 * 16);
        scanFix_kernel<<<dim3(8, 96), 128>>>();
        scanB_kernel<<<dim3(8, 6, NCHK), 128>>>(dts, xc, xdbl,
                                                A_log + (long)layer * 4 * 768 * 16,
                                                Ds + (long)layer * 4 * 768, ys);
        combine_kernel<<<2048, 256>>>(ys, xz, on_w + layer * 768, on_b + layer * 768);
        // out_proj + residual: (2048 x 384 x 768), split-K x4 atomics onto xh
        gemm_bf<<<dim3(6, 32, 4), 256>>>(yh, yl, whi + W_OUT + (long)layer * 294912,
                                         wlo + W_OUT + (long)layer * 294912, nullptr, xh,
                                         nullptr, nullptr, 2048, 384, 768, 768, 768, 384,
                                         0, 0, 1, 0, 0, nullptr, 0, 4, 4);
    }

    transpose_kernel<<<dim3(12, 32, 2), dim3(32, 8)>>>(xh, out, 1024, 384);
}